// round 3
// baseline (speedup 1.0000x reference)
#include <cuda_runtime.h>
#include <cstdint>
#include <cstddef>

#define D_MODEL 1024
#define SEQ     2048
#define NB      2
#define NH      16
#define HD      64
#define MROWS   4096   // NB * SEQ

// Scratch (allocation rules: __device__ globals only)
__device__ float g_qkv[(size_t)MROWS * 3072];   // [row][ Q(1024) | K(1024) | V(1024) ]
__device__ float g_att[(size_t)MROWS * 1024];   // attention output, [B*T][H*Dh]

typedef unsigned long long ull;

__device__ __forceinline__ ull ffma2(ull a, ull b, ull c) {
    ull d;
    asm("fma.rn.f32x2 %0, %1, %2, %3;" : "=l"(d) : "l"(a), "l"(b), "l"(c));
    return d;
}
__device__ __forceinline__ float2 unpack2(ull v) {
    float2 f;
    asm("mov.b64 {%0, %1}, %2;" : "=f"(f.x), "=f"(f.y) : "l"(v));
    return f;
}

// ---------------------------------------------------------------------------
// GEMM: C[m, ccol0 + n] = sum_k A[m,k] * Wt[n,k]   (Wt pre-offset to col tile)
// 128x128 block tile, 256 threads, 8x8 per thread, FFMA2 inner loop.
// A stored DUPLICATED in smem so ld.shared.v2.u64 yields (a,a) packed pairs.
// ---------------------------------------------------------------------------
template<bool HAS_BIAS>
__device__ __forceinline__ void gemm_body(
    const float* __restrict__ A,
    const float* __restrict__ Wt,
    float* __restrict__ C, int ldc, int ccol0,
    const float* __restrict__ bias)
{
    __shared__ float As2[16][260];   // [k][2*m], each A value stored twice
    __shared__ float Bs[16][132];    // [k][n]

    const int tid = threadIdx.x;
    const int lr  = tid >> 2;          // 0..63
    const int lc  = (tid & 3) << 2;    // 0,4,8,12
    const int ty  = tid >> 4;          // 0..15  -> rows ty*8..+7
    const int tx  = tid & 15;          // 0..15  -> cols tx*8..+7
    const int mtile = blockIdx.x;

    const float* Ap = A  + (size_t)(mtile * 128 + lr) * D_MODEL + lc;
    const float* Bp = Wt + (size_t)lr * D_MODEL + lc;

    float4 ra0 = *(const float4*)(Ap);
    float4 ra1 = *(const float4*)(Ap + 64 * D_MODEL);
    float4 rb0 = *(const float4*)(Bp);
    float4 rb1 = *(const float4*)(Bp + 64 * D_MODEL);

    ull acc[8][4];
    #pragma unroll
    for (int i = 0; i < 8; i++)
        #pragma unroll
        for (int n = 0; n < 4; n++) acc[i][n] = 0ULL;

    #pragma unroll 1
    for (int kt = 0; kt < D_MODEL / 16; kt++) {
        __syncthreads();
        {
            float av[4] = {ra0.x, ra0.y, ra0.z, ra0.w};
            float aw[4] = {ra1.x, ra1.y, ra1.z, ra1.w};
            float bv[4] = {rb0.x, rb0.y, rb0.z, rb0.w};
            float bw[4] = {rb1.x, rb1.y, rb1.z, rb1.w};
            #pragma unroll
            for (int j = 0; j < 4; j++) {
                As2[lc + j][2 * lr]       = av[j];
                As2[lc + j][2 * lr + 1]   = av[j];
                As2[lc + j][2 * lr + 128] = aw[j];
                As2[lc + j][2 * lr + 129] = aw[j];
                Bs[lc + j][lr]      = bv[j];
                Bs[lc + j][lr + 64] = bw[j];
            }
        }
        __syncthreads();
        if (kt < D_MODEL / 16 - 1) {   // software-pipelined global prefetch
            Ap += 16; Bp += 16;
            ra0 = *(const float4*)(Ap);
            ra1 = *(const float4*)(Ap + 64 * D_MODEL);
            rb0 = *(const float4*)(Bp);
            rb1 = *(const float4*)(Bp + 64 * D_MODEL);
        }
        #pragma unroll
        for (int kk = 0; kk < 16; kk++) {
            ulonglong2 A01 = *(const ulonglong2*)&As2[kk][2 * (ty * 8)];
            ulonglong2 A23 = *(const ulonglong2*)&As2[kk][2 * (ty * 8) + 4];
            ulonglong2 A45 = *(const ulonglong2*)&As2[kk][2 * (ty * 8) + 8];
            ulonglong2 A67 = *(const ulonglong2*)&As2[kk][2 * (ty * 8) + 12];
            ulonglong2 B03 = *(const ulonglong2*)&Bs[kk][tx * 8];
            ulonglong2 B47 = *(const ulonglong2*)&Bs[kk][tx * 8 + 4];
            ull ad[8] = {A01.x, A01.y, A23.x, A23.y, A45.x, A45.y, A67.x, A67.y};
            ull bp[4] = {B03.x, B03.y, B47.x, B47.y};
            #pragma unroll
            for (int i = 0; i < 8; i++) {
                #pragma unroll
                for (int n = 0; n < 4; n++)
                    acc[i][n] = ffma2(ad[i], bp[n], acc[i][n]);
            }
        }
    }

    const int row0 = mtile * 128 + ty * 8;
    #pragma unroll
    for (int i = 0; i < 8; i++) {
        #pragma unroll
        for (int n = 0; n < 4; n++) {
            float2 v = unpack2(acc[i][n]);
            int col = ccol0 + tx * 8 + 2 * n;
            if (HAS_BIAS) { v.x += bias[col]; v.y += bias[col + 1]; }
            *(float2*)(C + (size_t)(row0 + i) * ldc + col) = v;
        }
    }
}

__global__ __launch_bounds__(256, 2) void qkv_kernel(
    const float* __restrict__ X, const float* __restrict__ Wq,
    const float* __restrict__ Wk, const float* __restrict__ Wv)
{
    int nt = blockIdx.y;  // 0..23 -> 8 tiles each of Q, K, V
    const float* W;
    if (nt < 8)       W = Wq + (size_t)nt * 128 * D_MODEL;
    else if (nt < 16) W = Wk + (size_t)(nt - 8) * 128 * D_MODEL;
    else              W = Wv + (size_t)(nt - 16) * 128 * D_MODEL;
    gemm_body<false>(X, W, g_qkv, 3072, nt * 128, nullptr);
}

__global__ __launch_bounds__(256, 2) void oproj_kernel(
    const float* __restrict__ Wo, const float* __restrict__ bo,
    float* __restrict__ out)
{
    gemm_body<true>(g_att, Wo + (size_t)blockIdx.y * 128 * D_MODEL,
                    out, 1024, blockIdx.y * 128, bo);
}

// ---------------------------------------------------------------------------
// RoPE (in place on Q and K halves of g_qkv)
// ---------------------------------------------------------------------------
__global__ void rope_kernel() {
    int idx = blockIdx.x * blockDim.x + threadIdx.x;  // [0, 4096*16*32)
    int d   = idx & 31;
    int h   = (idx >> 5) & 15;
    int row = idx >> 9;
    if (row >= MROWS) return;
    int t = row & (SEQ - 1);

    float expo = (float)(2 * d) * (1.0f / 64.0f);
    float inv  = expf(expo * -9.210340371976184f);   // 10000^{-2d/64}
    float ang  = (float)t * inv;
    float s, c;
    sincosf(ang, &s, &c);

    float* base = g_qkv + (size_t)row * 3072 + h * 64 + d;
    float x1 = base[0],    x2 = base[32];
    base[0]    = x1 * c - x2 * s;
    base[32]   = x2 * c + x1 * s;
    x1 = base[1024];  x2 = base[1056];
    base[1024] = x1 * c - x2 * s;
    base[1056] = x2 * c + x1 * s;
}

// ---------------------------------------------------------------------------
// Sliding-window attention: one block per (qtile of 64, head, batch).
// 3 key chunks of 64 cover [q0-128, q0+63]; masking enforces the exact window.
// Smem exactly 48 KB static (Q, K/P aliased, V) -> 4 CTAs/SM, no attr calls.
// ---------------------------------------------------------------------------
__global__ __launch_bounds__(256) void attn_kernel() {
    __shared__ float Qs[64 * 64];    // [q][d], stride 64 (reads are broadcast)
    __shared__ float KPs[64 * 64];   // K (swizzled) then aliased as P tile
    __shared__ float Vs[64 * 64];    // [k][d]

    const int tid = threadIdx.x;
    const int tx  = tid & 15;        // -> keys tx*4..+3 / dims tx*4..+3
    const int ty  = tid >> 4;        // -> query rows ty*4..+3
    const int t0  = blockIdx.x * 64;
    const int h   = blockIdx.y;
    const int b   = blockIdx.z;
    const int lr  = tid >> 2;        // loader row 0..63
    const int lq  = tid & 3;         // loader quad

    // load Q tile
    {
        const float* Qg = g_qkv + (size_t)(b * SEQ + t0 + lr) * 3072 + h * 64;
        #pragma unroll
        for (int j = 0; j < 4; j++) {
            float4 v = *(const float4*)(Qg + lq * 16 + j * 4);
            *(float4*)(Qs + lr * 64 + lq * 16 + j * 4) = v;
        }
    }

    float m[4], l[4], acc[4][4];
    #pragma unroll
    for (int i = 0; i < 4; i++) {
        m[i] = -1e30f; l[i] = 0.f;
        #pragma unroll
        for (int j = 0; j < 4; j++) acc[i][j] = 0.f;
    }

    for (int cch = 0; cch < 3; cch++) {
        const int ks0 = t0 - 128 + cch * 64;
        if (ks0 < 0) continue;                       // uniform across block

        __syncthreads();                             // prev PV done; Qs visible
        {   // load K chunk (column-swizzled) and V chunk
            const float* Kg = g_qkv + (size_t)(b * SEQ + ks0 + lr) * 3072 + 1024 + h * 64;
            const float* Vg = Kg + 1024;
            const int rsw = lr >> 2;
            #pragma unroll
            for (int j = 0; j < 4; j++) {
                int c4 = lq * 4 + j;                 // logical d-chunk 0..15
                float4 kv = *(const float4*)(Kg + c4 * 4);
                int phys = (c4 + rsw) & 15;          // swizzle: conflict-free reads
                *(float4*)(KPs + lr * 64 + phys * 4) = kv;
                float4 vv = *(const float4*)(Vg + c4 * 4);
                *(float4*)(Vs + lr * 64 + c4 * 4) = vv;
            }
        }
        __syncthreads();

        // S = Q K^T  (4x4 register tile per thread)
        float s[4][4];
        #pragma unroll
        for (int i = 0; i < 4; i++)
            #pragma unroll
            for (int j = 0; j < 4; j++) s[i][j] = 0.f;

        #pragma unroll
        for (int d4 = 0; d4 < 16; d4++) {
            float4 qv[4], kv[4];
            #pragma unroll
            for (int i = 0; i < 4; i++)
                qv[i] = *(const float4*)(Qs + (ty * 4 + i) * 64 + d4 * 4);
            const int phys = ((d4 + tx) & 15) * 4;   // row>>2 == tx for rows tx*4+j
            #pragma unroll
            for (int j = 0; j < 4; j++)
                kv[j] = *(const float4*)(KPs + (tx * 4 + j) * 64 + phys);
            #pragma unroll
            for (int i = 0; i < 4; i++)
                #pragma unroll
                for (int j = 0; j < 4; j++)
                    s[i][j] += qv[i].x * kv[j].x + qv[i].y * kv[j].y
                             + qv[i].z * kv[j].z + qv[i].w * kv[j].w;
        }
        __syncthreads();   // everyone done reading K before P overwrites it

        // scale + window mask + online softmax; write P into KPs
        #pragma unroll
        for (int i = 0; i < 4; i++) {
            const int qg = t0 + ty * 4 + i;
            float sv[4];
            float mloc = -1e30f;
            #pragma unroll
            for (int j = 0; j < 4; j++) {
                int kg = ks0 + tx * 4 + j;
                float val = s[i][j] * 0.125f;        // Dh^{-1/2}
                if (kg > qg || kg < qg - 127) val = -1e30f;
                sv[j] = val;
                mloc = fmaxf(mloc, val);
            }
            #pragma unroll
            for (int off = 8; off >= 1; off >>= 1)
                mloc = fmaxf(mloc, __shfl_xor_sync(0xffffffffu, mloc, off));
            float mn    = fmaxf(m[i], mloc);
            float alpha = __expf(m[i] - mn);
            float pj[4], psum = 0.f;
            #pragma unroll
            for (int j = 0; j < 4; j++) { pj[j] = __expf(sv[j] - mn); psum += pj[j]; }
            #pragma unroll
            for (int off = 8; off >= 1; off >>= 1)
                psum += __shfl_xor_sync(0xffffffffu, psum, off);
            m[i] = mn;
            l[i] = l[i] * alpha + psum;
            #pragma unroll
            for (int j = 0; j < 4; j++) acc[i][j] *= alpha;
            float4 pv; pv.x = pj[0]; pv.y = pj[1]; pv.z = pj[2]; pv.w = pj[3];
            *(float4*)(KPs + (ty * 4 + i) * 64 + tx * 4) = pv;
        }
        __syncthreads();

        // O += P V
        #pragma unroll
        for (int k4 = 0; k4 < 16; k4++) {
            float pa[4][4];
            #pragma unroll
            for (int i = 0; i < 4; i++) {
                float4 t = *(const float4*)(KPs + (ty * 4 + i) * 64 + k4 * 4);
                pa[i][0] = t.x; pa[i][1] = t.y; pa[i][2] = t.z; pa[i][3] = t.w;
            }
            #pragma unroll
            for (int kk = 0; kk < 4; kk++) {
                float4 vv = *(const float4*)(Vs + (k4 * 4 + kk) * 64 + tx * 4);
                #pragma unroll
                for (int i = 0; i < 4; i++) {
                    acc[i][0] += pa[i][kk] * vv.x;
                    acc[i][1] += pa[i][kk] * vv.y;
                    acc[i][2] += pa[i][kk] * vv.z;
                    acc[i][3] += pa[i][kk] * vv.w;
                }
            }
        }
    }

    // epilogue: normalize and write to g_att
    #pragma unroll
    for (int i = 0; i < 4; i++) {
        float invl = 1.0f / l[i];
        float4 o;
        o.x = acc[i][0] * invl; o.y = acc[i][1] * invl;
        o.z = acc[i][2] * invl; o.w = acc[i][3] * invl;
        *(float4*)(g_att + (size_t)(b * SEQ + t0 + ty * 4 + i) * 1024
                         + h * 64 + tx * 4) = o;
    }
}

// ---------------------------------------------------------------------------
extern "C" void kernel_launch(void* const* d_in, const int* in_sizes, int n_in,
                              void* d_out, int out_size) {
    (void)in_sizes; (void)n_in; (void)out_size;
    const float* X  = (const float*)d_in[0];
    const float* Wq = (const float*)d_in[1];
    const float* Wk = (const float*)d_in[2];
    const float* Wv = (const float*)d_in[3];
    const float* Wo = (const float*)d_in[4];
    const float* bo = (const float*)d_in[5];
    float* out = (float*)d_out;

    qkv_kernel<<<dim3(32, 24), 256>>>(X, Wq, Wk, Wv);
    rope_kernel<<<(MROWS * NH * 32) / 256, 256>>>();
    attn_kernel<<<dim3(SEQ / 64, NH, NB), 256>>>();
    oproj_kernel<<<dim3(32, 8), 256>>>(Wo, bo, out);
}

// round 6
// speedup vs baseline: 2.2073x; 2.2073x over previous
#include <cuda_runtime.h>
#include <cuda_bf16.h>
#include <cstdint>
#include <cstddef>

#define D_MODEL 1024
#define SEQ     2048
#define NB      2
#define NH      16
#define MROWS   4096   // NB * SEQ

// ---------------- scratch (device globals only — no allocs allowed) --------
__device__ float g_qkv[(size_t)MROWS * 3072];   // [row][ Q | K | V ]
__device__ __nv_bfloat16 g_xh[(size_t)MROWS * 1024];
__device__ __nv_bfloat16 g_xl[(size_t)MROWS * 1024];
__device__ __nv_bfloat16 g_wh[(size_t)3072 * 1024];   // Wq|Wk|Wv stacked [n][k]
__device__ __nv_bfloat16 g_wl[(size_t)3072 * 1024];
__device__ __nv_bfloat16 g_oh[(size_t)1024 * 1024];   // Wo [n][k]
__device__ __nv_bfloat16 g_ol[(size_t)1024 * 1024];
__device__ __nv_bfloat16 g_ah[(size_t)MROWS * 1024];  // attn out hi/lo
__device__ __nv_bfloat16 g_al[(size_t)MROWS * 1024];

// ---------------- helpers ---------------------------------------------------
__device__ __forceinline__ uint32_t smem_u32(const void* p) {
    uint32_t a;
    asm("{ .reg .u64 t; cvta.to.shared.u64 t, %1; cvt.u32.u64 %0, t; }"
        : "=r"(a) : "l"(p));
    return a;
}
__device__ __forceinline__ void cp_async16(uint32_t so, const void* gp) {
    asm volatile("cp.async.cg.shared.global [%0], [%1], 16;"
                 :: "r"(so), "l"(gp) : "memory");
}
__device__ __forceinline__ void ldm4(uint32_t* r, uint32_t a) {
    asm volatile("ldmatrix.sync.aligned.m8n8.x4.shared.b16 {%0,%1,%2,%3}, [%4];"
                 : "=r"(r[0]), "=r"(r[1]), "=r"(r[2]), "=r"(r[3]) : "r"(a));
}
__device__ __forceinline__ void mma16816(float* c, const uint32_t* a,
                                         const uint32_t* b) {
    asm volatile(
        "mma.sync.aligned.m16n8k16.row.col.f32.bf16.bf16.f32 "
        "{%0,%1,%2,%3}, {%4,%5,%6,%7}, {%8,%9}, {%0,%1,%2,%3};"
        : "+f"(c[0]), "+f"(c[1]), "+f"(c[2]), "+f"(c[3])
        : "r"(a[0]), "r"(a[1]), "r"(a[2]), "r"(a[3]), "r"(b[0]), "r"(b[1]));
}

// ---------------- HMMA GEMM: C[m][n] = sum_k A[m][k]*B[n][k], hi/lo bf16 ----
// CTA tile 128x128, 8 warps (4M x 2N), warp tile 32x64, K-chunk 32,
// 3-stage cp.async pipeline, rows padded to 80B (conflict-free ldmatrix).
#define KCH     32
#define TILE_B  10240            // 128 rows * 80B
#define STAGE_B 40960            // Ah|Al|Bh|Bl
#define NSTAGE  3
#define GSMEM_B (NSTAGE * STAGE_B)   // 122880

template<bool HAS_BIAS>
__device__ __forceinline__ void gemm_hmma_body(
    const __nv_bfloat16* __restrict__ Ah_, const __nv_bfloat16* __restrict__ Al_,
    const __nv_bfloat16* __restrict__ Bh_, const __nv_bfloat16* __restrict__ Bl_,
    float* __restrict__ C, int ldc, const float* __restrict__ bias)
{
    extern __shared__ __align__(16) char smem[];
    const uint32_t sb = smem_u32(smem);
    const int tid = threadIdx.x, lid = tid & 31, wid = tid >> 5;
    const int wm = wid >> 1, wn = wid & 1;
    const int mtile = blockIdx.x, ntile = blockIdx.y;

    const __nv_bfloat16* baseT[4] = {
        Ah_ + (size_t)mtile * 128 * 1024, Al_ + (size_t)mtile * 128 * 1024,
        Bh_ + (size_t)ntile * 128 * 1024, Bl_ + (size_t)ntile * 128 * 1024 };

    // per-lane ldmatrix offsets (bytes)
    const int rowA = (lid & 7) + 8 * ((lid >> 3) & 1);
    const uint32_t aoff = (uint32_t)(wm * 32 + rowA) * 80 + ((lid >> 4) & 1) * 16;
    const int nB = (lid & 7) + 8 * ((lid >> 4) & 1);
    const uint32_t boff = (uint32_t)(wn * 64 + nB) * 80 + ((lid >> 3) & 1) * 16;

    float acc[2][8][4];
    #pragma unroll
    for (int mi = 0; mi < 2; mi++)
        #pragma unroll
        for (int nj = 0; nj < 8; nj++)
            #pragma unroll
            for (int q = 0; q < 4; q++) acc[mi][nj][q] = 0.f;

    auto load_chunk = [&](int kc, int stage) {
        uint32_t st = sb + stage * STAGE_B;
        #pragma unroll
        for (int v = 0; v < 8; v++) {
            int t   = v >> 1;                        // tile 0..3
            int idx = ((v & 1) << 8) | tid;          // 0..511 within tile
            int r   = idx >> 2;                      // row 0..127
            int g   = idx & 3;                       // 16B granule
            const __nv_bfloat16* gp = baseT[t] + (size_t)r * 1024 + kc * KCH + g * 8;
            cp_async16(st + t * TILE_B + r * 80 + g * 16, gp);
        }
    };

    load_chunk(0, 0);
    asm volatile("cp.async.commit_group;" ::: "memory");
    load_chunk(1, 1);
    asm volatile("cp.async.commit_group;" ::: "memory");

    for (int i = 0; i < 32; i++) {
        asm volatile("cp.async.wait_group 1;" ::: "memory");
        __syncthreads();
        if (i + 2 < 32) load_chunk(i + 2, (i + 2) % 3);
        asm volatile("cp.async.commit_group;" ::: "memory");

        const uint32_t st = sb + (i % 3) * STAGE_B;
        #pragma unroll
        for (int ks = 0; ks < 2; ks++) {
            uint32_t ah[2][4], al[2][4];
            #pragma unroll
            for (int mi = 0; mi < 2; mi++) {
                ldm4(ah[mi], st + mi * 1280 + ks * 32 + aoff);
                ldm4(al[mi], st + TILE_B + mi * 1280 + ks * 32 + aoff);
            }
            uint32_t bh[8][2], bl[8][2];
            #pragma unroll
            for (int nb = 0; nb < 4; nb++) {
                uint32_t r[4];
                ldm4(r, st + 2 * TILE_B + nb * 1280 + ks * 32 + boff);
                bh[2 * nb][0] = r[0]; bh[2 * nb][1] = r[1];
                bh[2 * nb + 1][0] = r[2]; bh[2 * nb + 1][1] = r[3];
                ldm4(r, st + 3 * TILE_B + nb * 1280 + ks * 32 + boff);
                bl[2 * nb][0] = r[0]; bl[2 * nb][1] = r[1];
                bl[2 * nb + 1][0] = r[2]; bl[2 * nb + 1][1] = r[3];
            }
            #pragma unroll
            for (int mi = 0; mi < 2; mi++)
                #pragma unroll
                for (int nj = 0; nj < 8; nj++) {
                    mma16816(acc[mi][nj], ah[mi], bh[nj]);   // Ah*Bh
                    mma16816(acc[mi][nj], ah[mi], bl[nj]);   // Ah*Bl
                    mma16816(acc[mi][nj], al[mi], bh[nj]);   // Al*Bh
                }
        }
    }

    // epilogue: C frag mapping — rows l/4 (+8), cols (l%4)*2 (+1)
    const int row0 = mtile * 128 + wm * 32 + (lid >> 2);
    const int col0 = ntile * 128 + wn * 64 + (lid & 3) * 2;
    #pragma unroll
    for (int mi = 0; mi < 2; mi++)
        #pragma unroll
        for (int nj = 0; nj < 8; nj++) {
            int r = row0 + mi * 16;
            int c = col0 + nj * 8;
            float b0 = 0.f, b1 = 0.f;
            if (HAS_BIAS) { b0 = bias[c]; b1 = bias[c + 1]; }
            float2 v0{acc[mi][nj][0] + b0, acc[mi][nj][1] + b1};
            float2 v1{acc[mi][nj][2] + b0, acc[mi][nj][3] + b1};
            *(float2*)(C + (size_t)r * ldc + c)       = v0;
            *(float2*)(C + (size_t)(r + 8) * ldc + c) = v1;
        }
}

__global__ __launch_bounds__(256, 1) void qkv_hmma() {
    gemm_hmma_body<false>(g_xh, g_xl, g_wh, g_wl, g_qkv, 3072, nullptr);
}
__global__ __launch_bounds__(256, 1) void oproj_hmma(float* __restrict__ out,
                                                     const float* __restrict__ bias) {
    gemm_hmma_body<true>(g_ah, g_al, g_oh, g_ol, out, 1024, bias);
}

// ---------------- fp32 -> bf16 hi/lo split ---------------------------------
__device__ __forceinline__ void split_body(const float* __restrict__ src,
                                           __nv_bfloat16* __restrict__ hi,
                                           __nv_bfloat16* __restrict__ lo, int n4) {
    int i = blockIdx.x * blockDim.x + threadIdx.x;
    if (i >= n4) return;
    float4 v = ((const float4*)src)[i];
    __nv_bfloat16 h0 = __float2bfloat16(v.x), h1 = __float2bfloat16(v.y);
    __nv_bfloat16 h2 = __float2bfloat16(v.z), h3 = __float2bfloat16(v.w);
    __nv_bfloat16 l0 = __float2bfloat16(v.x - __bfloat162float(h0));
    __nv_bfloat16 l1 = __float2bfloat16(v.y - __bfloat162float(h1));
    __nv_bfloat16 l2 = __float2bfloat16(v.z - __bfloat162float(h2));
    __nv_bfloat16 l3 = __float2bfloat16(v.w - __bfloat162float(h3));
    __nv_bfloat162 hp0{h0, h1}, hp1{h2, h3}, lp0{l0, l1}, lp1{l2, l3};
    uint2 hv, lv;
    hv.x = *(uint32_t*)&hp0; hv.y = *(uint32_t*)&hp1;
    lv.x = *(uint32_t*)&lp0; lv.y = *(uint32_t*)&lp1;
    ((uint2*)hi)[i] = hv;
    ((uint2*)lo)[i] = lv;
}
__global__ void split_x(const float* __restrict__ src) {
    split_body(src, g_xh, g_xl, MROWS * 1024 / 4);
}
__global__ void split_w(const float* __restrict__ src, int rowoff) {
    split_body(src, g_wh + (size_t)rowoff * 1024, g_wl + (size_t)rowoff * 1024,
               1024 * 1024 / 4);
}
__global__ void split_wo(const float* __restrict__ src) {
    split_body(src, g_oh, g_ol, 1024 * 1024 / 4);
}

// ---------------- RoPE (in place on Q and K halves of g_qkv) ---------------
__global__ void rope_kernel() {
    int idx = blockIdx.x * blockDim.x + threadIdx.x;
    int d   = idx & 31;
    int h   = (idx >> 5) & 15;
    int row = idx >> 9;
    if (row >= MROWS) return;
    int t = row & (SEQ - 1);

    float expo = (float)(2 * d) * (1.0f / 64.0f);
    float inv  = expf(expo * -9.210340371976184f);
    float ang  = (float)t * inv;
    float s, c;
    sincosf(ang, &s, &c);

    float* base = g_qkv + (size_t)row * 3072 + h * 64 + d;
    float x1 = base[0],    x2 = base[32];
    base[0]    = x1 * c - x2 * s;
    base[32]   = x2 * c + x1 * s;
    x1 = base[1024];  x2 = base[1056];
    base[1024] = x1 * c - x2 * s;
    base[1056] = x2 * c + x1 * s;
}

// ---------------- sliding-window attention (fp32; bf16 hi/lo epilogue) -----
__global__ __launch_bounds__(256) void attn_kernel() {
    __shared__ float Qs[64 * 64];
    __shared__ float KPs[64 * 64];
    __shared__ float Vs[64 * 64];

    const int tid = threadIdx.x;
    const int tx  = tid & 15;
    const int ty  = tid >> 4;
    const int t0  = blockIdx.x * 64;
    const int h   = blockIdx.y;
    const int b   = blockIdx.z;
    const int lr  = tid >> 2;
    const int lq  = tid & 3;

    {
        const float* Qg = g_qkv + (size_t)(b * SEQ + t0 + lr) * 3072 + h * 64;
        #pragma unroll
        for (int j = 0; j < 4; j++) {
            float4 v = *(const float4*)(Qg + lq * 16 + j * 4);
            *(float4*)(Qs + lr * 64 + lq * 16 + j * 4) = v;
        }
    }

    float m[4], l[4], acc[4][4];
    #pragma unroll
    for (int i = 0; i < 4; i++) {
        m[i] = -1e30f; l[i] = 0.f;
        #pragma unroll
        for (int j = 0; j < 4; j++) acc[i][j] = 0.f;
    }

    for (int cch = 0; cch < 3; cch++) {
        const int ks0 = t0 - 128 + cch * 64;
        if (ks0 < 0) continue;

        __syncthreads();
        {
            const float* Kg = g_qkv + (size_t)(b * SEQ + ks0 + lr) * 3072 + 1024 + h * 64;
            const float* Vg = Kg + 1024;
            const int rsw = lr >> 2;
            #pragma unroll
            for (int j = 0; j < 4; j++) {
                int c4 = lq * 4 + j;
                float4 kv = *(const float4*)(Kg + c4 * 4);
                int phys = (c4 + rsw) & 15;
                *(float4*)(KPs + lr * 64 + phys * 4) = kv;
                float4 vv = *(const float4*)(Vg + c4 * 4);
                *(float4*)(Vs + lr * 64 + c4 * 4) = vv;
            }
        }
        __syncthreads();

        float s[4][4];
        #pragma unroll
        for (int i = 0; i < 4; i++)
            #pragma unroll
            for (int j = 0; j < 4; j++) s[i][j] = 0.f;

        #pragma unroll
        for (int d4 = 0; d4 < 16; d4++) {
            float4 qv[4], kv[4];
            #pragma unroll
            for (int i = 0; i < 4; i++)
                qv[i] = *(const float4*)(Qs + (ty * 4 + i) * 64 + d4 * 4);
            const int phys = ((d4 + tx) & 15) * 4;
            #pragma unroll
            for (int j = 0; j < 4; j++)
                kv[j] = *(const float4*)(KPs + (tx * 4 + j) * 64 + phys);
            #pragma unroll
            for (int i = 0; i < 4; i++)
                #pragma unroll
                for (int j = 0; j < 4; j++)
                    s[i][j] += qv[i].x * kv[j].x + qv[i].y * kv[j].y
                             + qv[i].z * kv[j].z + qv[i].w * kv[j].w;
        }
        __syncthreads();

        #pragma unroll
        for (int i = 0; i < 4; i++) {
            const int qg = t0 + ty * 4 + i;
            float sv[4];
            float mloc = -1e30f;
            #pragma unroll
            for (int j = 0; j < 4; j++) {
                int kg = ks0 + tx * 4 + j;
                float val = s[i][j] * 0.125f;
                if (kg > qg || kg < qg - 127) val = -1e30f;
                sv[j] = val;
                mloc = fmaxf(mloc, val);
            }
            #pragma unroll
            for (int off = 8; off >= 1; off >>= 1)
                mloc = fmaxf(mloc, __shfl_xor_sync(0xffffffffu, mloc, off));
            float mn    = fmaxf(m[i], mloc);
            float alpha = __expf(m[i] - mn);
            float pj[4], psum = 0.f;
            #pragma unroll
            for (int j = 0; j < 4; j++) { pj[j] = __expf(sv[j] - mn); psum += pj[j]; }
            #pragma unroll
            for (int off = 8; off >= 1; off >>= 1)
                psum += __shfl_xor_sync(0xffffffffu, psum, off);
            m[i] = mn;
            l[i] = l[i] * alpha + psum;
            #pragma unroll
            for (int j = 0; j < 4; j++) acc[i][j] *= alpha;
            float4 pv; pv.x = pj[0]; pv.y = pj[1]; pv.z = pj[2]; pv.w = pj[3];
            *(float4*)(KPs + (ty * 4 + i) * 64 + tx * 4) = pv;
        }
        __syncthreads();

        #pragma unroll
        for (int k4 = 0; k4 < 16; k4++) {
            float pa[4][4];
            #pragma unroll
            for (int i = 0; i < 4; i++) {
                float4 t = *(const float4*)(KPs + (ty * 4 + i) * 64 + k4 * 4);
                pa[i][0] = t.x; pa[i][1] = t.y; pa[i][2] = t.z; pa[i][3] = t.w;
            }
            #pragma unroll
            for (int kk = 0; kk < 4; kk++) {
                float4 vv = *(const float4*)(Vs + (k4 * 4 + kk) * 64 + tx * 4);
                #pragma unroll
                for (int i = 0; i < 4; i++) {
                    acc[i][0] += pa[i][kk] * vv.x;
                    acc[i][1] += pa[i][kk] * vv.y;
                    acc[i][2] += pa[i][kk] * vv.z;
                    acc[i][3] += pa[i][kk] * vv.w;
                }
            }
        }
    }

    // epilogue: normalize and emit bf16 hi/lo directly (feeds oproj_hmma)
    #pragma unroll
    for (int i = 0; i < 4; i++) {
        float invl = 1.0f / l[i];
        float o0 = acc[i][0] * invl, o1 = acc[i][1] * invl;
        float o2 = acc[i][2] * invl, o3 = acc[i][3] * invl;
        __nv_bfloat16 h0 = __float2bfloat16(o0), h1 = __float2bfloat16(o1);
        __nv_bfloat16 h2 = __float2bfloat16(o2), h3 = __float2bfloat16(o3);
        __nv_bfloat16 l0 = __float2bfloat16(o0 - __bfloat162float(h0));
        __nv_bfloat16 l1 = __float2bfloat16(o1 - __bfloat162float(h1));
        __nv_bfloat16 l2 = __float2bfloat16(o2 - __bfloat162float(h2));
        __nv_bfloat16 l3 = __float2bfloat16(o3 - __bfloat162float(h3));
        size_t off = (size_t)(b * SEQ + t0 + ty * 4 + i) * 1024 + h * 64 + tx * 4;
        __nv_bfloat162 hp0{h0, h1}, hp1{h2, h3}, lp0{l0, l1}, lp1{l2, l3};
        uint2 hv, lv;
        hv.x = *(uint32_t*)&hp0; hv.y = *(uint32_t*)&hp1;
        lv.x = *(uint32_t*)&lp0; lv.y = *(uint32_t*)&lp1;
        *(uint2*)(g_ah + off) = hv;
        *(uint2*)(g_al + off) = lv;
    }
}

// ---------------------------------------------------------------------------
extern "C" void kernel_launch(void* const* d_in, const int* in_sizes, int n_in,
                              void* d_out, int out_size) {
    (void)in_sizes; (void)n_in; (void)out_size;
    const float* X  = (const float*)d_in[0];
    const float* Wq = (const float*)d_in[1];
    const float* Wk = (const float*)d_in[2];
    const float* Wv = (const float*)d_in[3];
    const float* Wo = (const float*)d_in[4];
    const float* bo = (const float*)d_in[5];
    float* out = (float*)d_out;

    cudaFuncSetAttribute(qkv_hmma,   cudaFuncAttributeMaxDynamicSharedMemorySize, GSMEM_B);
    cudaFuncSetAttribute(oproj_hmma, cudaFuncAttributeMaxDynamicSharedMemorySize, GSMEM_B);

    split_x<<<(MROWS * 1024 / 4 + 255) / 256, 256>>>(X);
    split_w<<<(1024 * 1024 / 4 + 255) / 256, 256>>>(Wq, 0);
    split_w<<<(1024 * 1024 / 4 + 255) / 256, 256>>>(Wk, 1024);
    split_w<<<(1024 * 1024 / 4 + 255) / 256, 256>>>(Wv, 2048);
    split_wo<<<(1024 * 1024 / 4 + 255) / 256, 256>>>(Wo);

    qkv_hmma<<<dim3(32, 24), 256, GSMEM_B>>>();
    rope_kernel<<<(MROWS * NH * 32) / 256, 256>>>();
    attn_kernel<<<dim3(SEQ / 64, NH, NB), 256>>>();
    oproj_hmma<<<dim3(32, 8), 256, GSMEM_B>>>(out, bo);
}

// round 8
// speedup vs baseline: 2.5359x; 1.1489x over previous
#include <cuda_runtime.h>
#include <cuda_bf16.h>
#include <cstdint>
#include <cstddef>

#define D_MODEL 1024
#define SEQ     2048
#define NB      2
#define NH      16
#define MROWS   4096   // NB * SEQ

// ---------------- scratch (device globals only — no allocs allowed) --------
__device__ __nv_bfloat16 g_h[(size_t)MROWS * 3072];   // Q|K|V hi (post-RoPE)
__device__ __nv_bfloat16 g_l[(size_t)MROWS * 3072];   // Q|K|V lo
__device__ __nv_bfloat16 g_xh[(size_t)MROWS * 1024];
__device__ __nv_bfloat16 g_xl[(size_t)MROWS * 1024];
__device__ __nv_bfloat16 g_wh[(size_t)3072 * 1024];   // Wq|Wk|Wv stacked [n][k]
__device__ __nv_bfloat16 g_wl[(size_t)3072 * 1024];
__device__ __nv_bfloat16 g_oh[(size_t)1024 * 1024];   // Wo [n][k]
__device__ __nv_bfloat16 g_ol[(size_t)1024 * 1024];
__device__ __nv_bfloat16 g_ah[(size_t)MROWS * 1024];  // attn out hi/lo
__device__ __nv_bfloat16 g_al[(size_t)MROWS * 1024];

// ---------------- helpers ---------------------------------------------------
__device__ __forceinline__ uint32_t smem_u32(const void* p) {
    uint32_t a;
    asm("{ .reg .u64 t; cvta.to.shared.u64 t, %1; cvt.u32.u64 %0, t; }"
        : "=r"(a) : "l"(p));
    return a;
}
__device__ __forceinline__ void cp_async16(uint32_t so, const void* gp) {
    asm volatile("cp.async.cg.shared.global [%0], [%1], 16;"
                 :: "r"(so), "l"(gp) : "memory");
}
__device__ __forceinline__ void ldm4(uint32_t* r, uint32_t a) {
    asm volatile("ldmatrix.sync.aligned.m8n8.x4.shared.b16 {%0,%1,%2,%3}, [%4];"
                 : "=r"(r[0]), "=r"(r[1]), "=r"(r[2]), "=r"(r[3]) : "r"(a));
}
__device__ __forceinline__ void ldm4t(uint32_t* r, uint32_t a) {
    asm volatile("ldmatrix.sync.aligned.m8n8.x4.trans.shared.b16 {%0,%1,%2,%3}, [%4];"
                 : "=r"(r[0]), "=r"(r[1]), "=r"(r[2]), "=r"(r[3]) : "r"(a));
}
__device__ __forceinline__ void mma16816(float* c, const uint32_t* a,
                                         const uint32_t* b) {
    asm volatile(
        "mma.sync.aligned.m16n8k16.row.col.f32.bf16.bf16.f32 "
        "{%0,%1,%2,%3}, {%4,%5,%6,%7}, {%8,%9}, {%0,%1,%2,%3};"
        : "+f"(c[0]), "+f"(c[1]), "+f"(c[2]), "+f"(c[3])
        : "r"(a[0]), "r"(a[1]), "r"(a[2]), "r"(a[3]), "r"(b[0]), "r"(b[1]));
}
__device__ __forceinline__ void pack_hl(float x, float y, uint32_t& hi, uint32_t& lo) {
    __nv_bfloat16 hx = __float2bfloat16(x), hy = __float2bfloat16(y);
    __nv_bfloat16 lx = __float2bfloat16(x - __bfloat162float(hx));
    __nv_bfloat16 ly = __float2bfloat16(y - __bfloat162float(hy));
    __nv_bfloat162 hp{hx, hy}, lp{lx, ly};
    hi = *(uint32_t*)&hp; lo = *(uint32_t*)&lp;
}

// ---------------- HMMA GEMM core (unchanged mainloop) ----------------------
#define KCH     32
#define TILE_B  10240            // 128 rows * 80B
#define STAGE_B 40960            // Ah|Al|Bh|Bl
#define NSTAGE  3
#define GSMEM_B (NSTAGE * STAGE_B)   // 122880

template<int MODE>   // 0 = qkv (RoPE + bf16 hi/lo out), 1 = oproj (fp32 + bias)
__device__ __forceinline__ void gemm_hmma_body(
    const __nv_bfloat16* __restrict__ Ah_, const __nv_bfloat16* __restrict__ Al_,
    const __nv_bfloat16* __restrict__ Bh_, const __nv_bfloat16* __restrict__ Bl_,
    float* __restrict__ C, const float* __restrict__ bias)
{
    extern __shared__ __align__(16) char smem[];
    const uint32_t sb = smem_u32(smem);
    const int tid = threadIdx.x, lid = tid & 31, wid = tid >> 5;
    const int wm = wid >> 1, wn = wid & 1;
    const int mtile = blockIdx.x, ntile = blockIdx.y;

    const __nv_bfloat16* baseT[4] = {
        Ah_ + (size_t)mtile * 128 * 1024, Al_ + (size_t)mtile * 128 * 1024,
        Bh_ + (size_t)ntile * 128 * 1024, Bl_ + (size_t)ntile * 128 * 1024 };

    const int rowA = (lid & 7) + 8 * ((lid >> 3) & 1);
    const uint32_t aoff = (uint32_t)(wm * 32 + rowA) * 80 + ((lid >> 4) & 1) * 16;
    const int nB = (lid & 7) + 8 * ((lid >> 4) & 1);
    const uint32_t boff = (uint32_t)(wn * 64 + nB) * 80 + ((lid >> 3) & 1) * 16;

    float acc[2][8][4];
    #pragma unroll
    for (int mi = 0; mi < 2; mi++)
        #pragma unroll
        for (int nj = 0; nj < 8; nj++)
            #pragma unroll
            for (int q = 0; q < 4; q++) acc[mi][nj][q] = 0.f;

    auto load_chunk = [&](int kc, int stage) {
        uint32_t st = sb + stage * STAGE_B;
        #pragma unroll
        for (int v = 0; v < 8; v++) {
            int t   = v >> 1;
            int idx = ((v & 1) << 8) | tid;
            int r   = idx >> 2;
            int g   = idx & 3;
            const __nv_bfloat16* gp = baseT[t] + (size_t)r * 1024 + kc * KCH + g * 8;
            cp_async16(st + t * TILE_B + r * 80 + g * 16, gp);
        }
    };

    load_chunk(0, 0);
    asm volatile("cp.async.commit_group;" ::: "memory");
    load_chunk(1, 1);
    asm volatile("cp.async.commit_group;" ::: "memory");

    for (int i = 0; i < 32; i++) {
        asm volatile("cp.async.wait_group 1;" ::: "memory");
        __syncthreads();
        if (i + 2 < 32) load_chunk(i + 2, (i + 2) % 3);
        asm volatile("cp.async.commit_group;" ::: "memory");

        const uint32_t st = sb + (i % 3) * STAGE_B;
        #pragma unroll
        for (int ks = 0; ks < 2; ks++) {
            uint32_t ah[2][4], al[2][4];
            #pragma unroll
            for (int mi = 0; mi < 2; mi++) {
                ldm4(ah[mi], st + mi * 1280 + ks * 32 + aoff);
                ldm4(al[mi], st + TILE_B + mi * 1280 + ks * 32 + aoff);
            }
            uint32_t bh[8][2], bl[8][2];
            #pragma unroll
            for (int nb = 0; nb < 4; nb++) {
                uint32_t r[4];
                ldm4(r, st + 2 * TILE_B + nb * 1280 + ks * 32 + boff);
                bh[2 * nb][0] = r[0]; bh[2 * nb][1] = r[1];
                bh[2 * nb + 1][0] = r[2]; bh[2 * nb + 1][1] = r[3];
                ldm4(r, st + 3 * TILE_B + nb * 1280 + ks * 32 + boff);
                bl[2 * nb][0] = r[0]; bl[2 * nb][1] = r[1];
                bl[2 * nb + 1][0] = r[2]; bl[2 * nb + 1][1] = r[3];
            }
            #pragma unroll
            for (int mi = 0; mi < 2; mi++)
                #pragma unroll
                for (int nj = 0; nj < 8; nj++) {
                    mma16816(acc[mi][nj], ah[mi], bh[nj]);
                    mma16816(acc[mi][nj], ah[mi], bl[nj]);
                    mma16816(acc[mi][nj], al[mi], bh[nj]);
                }
        }
    }

    const int row0 = mtile * 128 + wm * 32 + (lid >> 2);
    const int col0 = ntile * 128 + wn * 64 + (lid & 3) * 2;

    if (MODE == 0) {
        // RoPE for Q (ntile<8) and K (8<=ntile<16); V passthrough
        if (ntile < 16) {
            #pragma unroll
            for (int mi = 0; mi < 2; mi++)
                #pragma unroll
                for (int nj = 0; nj < 4; nj++)
                    #pragma unroll
                    for (int q = 0; q < 4; q++) {
                        int d = nj * 8 + (lid & 3) * 2 + (q & 1);        // 0..31
                        int t = (row0 + mi * 16 + ((q >> 1) ? 8 : 0)) & (SEQ - 1);
                        float inv = expf((float)(2 * d) * (1.0f / 64.0f)
                                         * -9.210340371976184f);
                        float sn, cs;
                        sincosf((float)t * inv, &sn, &cs);
                        float x1 = acc[mi][nj][q], x2 = acc[mi][nj + 4][q];
                        acc[mi][nj][q]     = x1 * cs - x2 * sn;
                        acc[mi][nj + 4][q] = x2 * cs + x1 * sn;
                    }
        }
        #pragma unroll
        for (int mi = 0; mi < 2; mi++)
            #pragma unroll
            for (int nj = 0; nj < 8; nj++) {
                size_t r = row0 + mi * 16;
                int c = col0 + nj * 8;
                uint32_t hv, lv;
                pack_hl(acc[mi][nj][0], acc[mi][nj][1], hv, lv);
                *(uint32_t*)(g_h + r * 3072 + c) = hv;
                *(uint32_t*)(g_l + r * 3072 + c) = lv;
                pack_hl(acc[mi][nj][2], acc[mi][nj][3], hv, lv);
                *(uint32_t*)(g_h + (r + 8) * 3072 + c) = hv;
                *(uint32_t*)(g_l + (r + 8) * 3072 + c) = lv;
            }
    } else {
        #pragma unroll
        for (int mi = 0; mi < 2; mi++)
            #pragma unroll
            for (int nj = 0; nj < 8; nj++) {
                size_t r = row0 + mi * 16;
                int c = col0 + nj * 8;
                float b0 = bias[c], b1 = bias[c + 1];
                float2 v0{acc[mi][nj][0] + b0, acc[mi][nj][1] + b1};
                float2 v1{acc[mi][nj][2] + b0, acc[mi][nj][3] + b1};
                *(float2*)(C + r * 1024 + c)       = v0;
                *(float2*)(C + (r + 8) * 1024 + c) = v1;
            }
    }
}

__global__ __launch_bounds__(256, 1) void qkv_hmma() {
    gemm_hmma_body<0>(g_xh, g_xl, g_wh, g_wl, nullptr, nullptr);
}
__global__ __launch_bounds__(256, 1) void oproj_hmma(float* __restrict__ out,
                                                     const float* __restrict__ bias) {
    gemm_hmma_body<1>(g_ah, g_al, g_oh, g_ol, out, bias);
}

// ---------------- fp32 -> bf16 hi/lo split ---------------------------------
__device__ __forceinline__ void split_one(const float* __restrict__ src,
                                          __nv_bfloat16* __restrict__ hi,
                                          __nv_bfloat16* __restrict__ lo, int i) {
    float4 v = ((const float4*)src)[i];
    uint2 hv, lv;
    pack_hl(v.x, v.y, hv.x, lv.x);
    pack_hl(v.z, v.w, hv.y, lv.y);
    ((uint2*)hi)[i] = hv;
    ((uint2*)lo)[i] = lv;
}
__global__ void split_x(const float* __restrict__ src) {
    int i = blockIdx.x * blockDim.x + threadIdx.x;
    if (i < MROWS * 1024 / 4) split_one(src, g_xh, g_xl, i);
}
__global__ void split_weights(const float* __restrict__ Wq, const float* __restrict__ Wk,
                              const float* __restrict__ Wv, const float* __restrict__ Wo) {
    int t = blockIdx.x >> 10;
    int i = (blockIdx.x & 1023) * blockDim.x + threadIdx.x;
    const float* src = (t == 0) ? Wq : (t == 1) ? Wk : (t == 2) ? Wv : Wo;
    __nv_bfloat16* hi = (t < 3) ? g_wh + (size_t)t * 1024 * 1024 : g_oh;
    __nv_bfloat16* lo = (t < 3) ? g_wl + (size_t)t * 1024 * 1024 : g_ol;
    if (i < 1024 * 1024 / 4) split_one(src, hi, lo, i);
}

// ---------------- sliding-window attention, HMMA hi/lo ----------------------
// 128 threads, 4 warps x m16 = 64 q rows per CTA. Smem 48KB static:
// Q/K/V each: hi 8KB + lo 8KB, 64 rows x 128B, XOR-swizzled 16B granules.
#define ASM_Q 0
#define ASM_K 16384
#define ASM_V 32768
#define SWZ(r, gd) ((r) * 128 + (((gd) ^ ((r) & 7)) * 16))

__global__ __launch_bounds__(128) void attn_kernel() {
    __shared__ __align__(16) char sm[49152];
    const uint32_t sb = smem_u32(sm);
    const int tid = threadIdx.x, lid = tid & 31, wid = tid >> 5;
    const int t0 = blockIdx.x * 64, h = blockIdx.y, b = blockIdx.z;

    // ---- load Q tile, build A-frags, keep for whole kernel ----
    {
        const size_t qr0 = (size_t)(b * SEQ + t0);
        #pragma unroll
        for (int it = 0; it < 4; it++) {
            int idx = it * 128 + tid;
            int r = idx >> 3, gd = idx & 7;
            uint32_t dst = sb + ASM_Q + SWZ(r, gd);
            cp_async16(dst,        g_h + (qr0 + r) * 3072 + h * 64 + gd * 8);
            cp_async16(dst + 8192, g_l + (qr0 + r) * 3072 + h * 64 + gd * 8);
        }
        asm volatile("cp.async.commit_group;\ncp.async.wait_group 0;" ::: "memory");
        __syncthreads();
    }
    uint32_t qh[4][4], ql[4][4];
    {
        int r = wid * 16 + (lid & 15);
        int gs = (lid >> 4) & 1;
        #pragma unroll
        for (int ks = 0; ks < 4; ks++) {
            uint32_t a = sb + ASM_Q + SWZ(r, ks * 2 + gs);
            ldm4(qh[ks], a);
            ldm4(ql[ks], a + 8192);
        }
    }

    float mmax0 = -1e30f, mmax1 = -1e30f, lsum0 = 0.f, lsum1 = 0.f;
    float o[8][4];
    #pragma unroll
    for (int nt = 0; nt < 8; nt++)
        #pragma unroll
        for (int q = 0; q < 4; q++) o[nt][q] = 0.f;

    const int qrow_a = t0 + wid * 16 + (lid >> 2);
    const int qrow_b = qrow_a + 8;

    for (int cch = 0; cch < 3; cch++) {
        const int ks0 = t0 - 128 + cch * 64;
        if (ks0 < 0) continue;

        __syncthreads();     // prior chunk's V frag reads complete
        {
            const size_t kr0 = (size_t)(b * SEQ + ks0);
            #pragma unroll
            for (int it = 0; it < 4; it++) {
                int idx = it * 128 + tid;
                int r = idx >> 3, gd = idx & 7;
                uint32_t sw = SWZ(r, gd);
                size_t go = (kr0 + r) * 3072 + h * 64 + gd * 8;
                cp_async16(sb + ASM_K + sw,        g_h + go + 1024);
                cp_async16(sb + ASM_K + 8192 + sw, g_l + go + 1024);
                cp_async16(sb + ASM_V + sw,        g_h + go + 2048);
                cp_async16(sb + ASM_V + 8192 + sw, g_l + go + 2048);
            }
            asm volatile("cp.async.commit_group;\ncp.async.wait_group 0;" ::: "memory");
            __syncthreads();
        }

        // ---- S = Q K^T (3-term hi/lo) ----
        float s[8][4];
        #pragma unroll
        for (int nt = 0; nt < 8; nt++)
            #pragma unroll
            for (int q = 0; q < 4; q++) s[nt][q] = 0.f;

        #pragma unroll
        for (int ks = 0; ks < 4; ks++) {
            const int n  = (lid & 7) + 8 * ((lid >> 4) & 1);
            const int gd = ks * 2 + ((lid >> 3) & 1);
            #pragma unroll
            for (int np = 0; np < 4; np++) {
                uint32_t kh[4], kl[4];
                int row = np * 16 + n;
                uint32_t a = sb + ASM_K + SWZ(row, gd);
                ldm4(kh, a);
                ldm4(kl, a + 8192);
                uint32_t bh0[2] = {kh[0], kh[1]}, bh1[2] = {kh[2], kh[3]};
                uint32_t bl0[2] = {kl[0], kl[1]}, bl1[2] = {kl[2], kl[3]};
                mma16816(s[2 * np],     qh[ks], bh0);
                mma16816(s[2 * np],     qh[ks], bl0);
                mma16816(s[2 * np],     ql[ks], bh0);
                mma16816(s[2 * np + 1], qh[ks], bh1);
                mma16816(s[2 * np + 1], qh[ks], bl1);
                mma16816(s[2 * np + 1], ql[ks], bh1);
            }
        }

        // ---- scale + mask + online softmax on frags ----
        float mloc0 = -1e30f, mloc1 = -1e30f;
        #pragma unroll
        for (int nt = 0; nt < 8; nt++)
            #pragma unroll
            for (int e = 0; e < 2; e++) {
                int kg = ks0 + nt * 8 + (lid & 3) * 2 + e;
                float v0 = s[nt][e] * 0.125f;
                float v1 = s[nt][2 + e] * 0.125f;
                if (kg > qrow_a || kg < qrow_a - 127) v0 = -1e30f;
                if (kg > qrow_b || kg < qrow_b - 127) v1 = -1e30f;
                s[nt][e] = v0; s[nt][2 + e] = v1;
                mloc0 = fmaxf(mloc0, v0);
                mloc1 = fmaxf(mloc1, v1);
            }
        mloc0 = fmaxf(mloc0, __shfl_xor_sync(0xffffffffu, mloc0, 1));
        mloc0 = fmaxf(mloc0, __shfl_xor_sync(0xffffffffu, mloc0, 2));
        mloc1 = fmaxf(mloc1, __shfl_xor_sync(0xffffffffu, mloc1, 1));
        mloc1 = fmaxf(mloc1, __shfl_xor_sync(0xffffffffu, mloc1, 2));
        float mn0 = fmaxf(mmax0, mloc0), mn1 = fmaxf(mmax1, mloc1);
        float al0 = __expf(mmax0 - mn0), al1 = __expf(mmax1 - mn1);
        float ps0 = 0.f, ps1 = 0.f;
        #pragma unroll
        for (int nt = 0; nt < 8; nt++)
            #pragma unroll
            for (int e = 0; e < 2; e++) {
                float p0 = __expf(s[nt][e] - mn0);
                float p1 = __expf(s[nt][2 + e] - mn1);
                s[nt][e] = p0; s[nt][2 + e] = p1;
                ps0 += p0; ps1 += p1;
            }
        ps0 += __shfl_xor_sync(0xffffffffu, ps0, 1);
        ps0 += __shfl_xor_sync(0xffffffffu, ps0, 2);
        ps1 += __shfl_xor_sync(0xffffffffu, ps1, 1);
        ps1 += __shfl_xor_sync(0xffffffffu, ps1, 2);
        mmax0 = mn0; mmax1 = mn1;
        lsum0 = lsum0 * al0 + ps0;
        lsum1 = lsum1 * al1 + ps1;
        #pragma unroll
        for (int nt = 0; nt < 8; nt++) {
            o[nt][0] *= al0; o[nt][1] *= al0;
            o[nt][2] *= al1; o[nt][3] *= al1;
        }

        // ---- P C-frags -> A-frags (registers only), hi/lo ----
        uint32_t ph[4][4], pl[4][4];
        #pragma unroll
        for (int ks = 0; ks < 4; ks++) {
            pack_hl(s[2 * ks][0],     s[2 * ks][1],     ph[ks][0], pl[ks][0]);
            pack_hl(s[2 * ks][2],     s[2 * ks][3],     ph[ks][1], pl[ks][1]);
            pack_hl(s[2 * ks + 1][0], s[2 * ks + 1][1], ph[ks][2], pl[ks][2]);
            pack_hl(s[2 * ks + 1][2], s[2 * ks + 1][3], ph[ks][3], pl[ks][3]);
        }

        // ---- O += P V (V via ldmatrix.trans, 3-term hi/lo) ----
        #pragma unroll
        for (int ks = 0; ks < 4; ks++) {
            const int tile = lid >> 3;
            const int r = ks * 16 + (tile & 1) * 8 + (lid & 7);
            #pragma unroll
            for (int dp = 0; dp < 4; dp++) {
                uint32_t vh[4], vl[4];
                uint32_t a = sb + ASM_V + SWZ(r, dp * 2 + (tile >> 1));
                ldm4t(vh, a);
                ldm4t(vl, a + 8192);
                uint32_t bh0[2] = {vh[0], vh[1]}, bh1[2] = {vh[2], vh[3]};
                uint32_t bl0[2] = {vl[0], vl[1]}, bl1[2] = {vl[2], vl[3]};
                mma16816(o[2 * dp],     ph[ks], bh0);
                mma16816(o[2 * dp],     ph[ks], bl0);
                mma16816(o[2 * dp],     pl[ks], bh0);
                mma16816(o[2 * dp + 1], ph[ks], bh1);
                mma16816(o[2 * dp + 1], ph[ks], bl1);
                mma16816(o[2 * dp + 1], pl[ks], bh1);
            }
        }
    }

    // ---- epilogue: normalize, emit bf16 hi/lo for oproj ----
    const float il0 = 1.0f / lsum0, il1 = 1.0f / lsum1;
    const size_t r0 = (size_t)(b * SEQ + t0 + wid * 16 + (lid >> 2));
    const size_t r1 = r0 + 8;
    const int c0 = h * 64 + (lid & 3) * 2;
    #pragma unroll
    for (int nt = 0; nt < 8; nt++) {
        int c = c0 + nt * 8;
        uint32_t hv, lv;
        pack_hl(o[nt][0] * il0, o[nt][1] * il0, hv, lv);
        *(uint32_t*)(g_ah + r0 * 1024 + c) = hv;
        *(uint32_t*)(g_al + r0 * 1024 + c) = lv;
        pack_hl(o[nt][2] * il1, o[nt][3] * il1, hv, lv);
        *(uint32_t*)(g_ah + r1 * 1024 + c) = hv;
        *(uint32_t*)(g_al + r1 * 1024 + c) = lv;
    }
}

// ---------------------------------------------------------------------------
extern "C" void kernel_launch(void* const* d_in, const int* in_sizes, int n_in,
                              void* d_out, int out_size) {
    (void)in_sizes; (void)n_in; (void)out_size;
    const float* X  = (const float*)d_in[0];
    const float* Wq = (const float*)d_in[1];
    const float* Wk = (const float*)d_in[2];
    const float* Wv = (const float*)d_in[3];
    const float* Wo = (const float*)d_in[4];
    const float* bo = (const float*)d_in[5];
    float* out = (float*)d_out;

    cudaFuncSetAttribute(qkv_hmma,   cudaFuncAttributeMaxDynamicSharedMemorySize, GSMEM_B);
    cudaFuncSetAttribute(oproj_hmma, cudaFuncAttributeMaxDynamicSharedMemorySize, GSMEM_B);

    split_x<<<4096, 256>>>(X);
    split_weights<<<4096, 256>>>(Wq, Wk, Wv, Wo);

    qkv_hmma<<<dim3(32, 24), 256, GSMEM_B>>>();
    attn_kernel<<<dim3(SEQ / 64, NH, NB), 128>>>();
    oproj_hmma<<<dim3(32, 8), 256, GSMEM_B>>>(out, bo);
}

// round 9
// speedup vs baseline: 2.7524x; 1.0854x over previous
#include <cuda_runtime.h>
#include <cuda_bf16.h>
#include <cstdint>
#include <cstddef>

#define D_MODEL 1024
#define SEQ     2048
#define NB      2
#define NH      16
#define MROWS   4096   // NB * SEQ

// ---------------- scratch (device globals only — no allocs allowed) --------
__device__ __nv_bfloat16 g_h[(size_t)MROWS * 3072];   // Q|K|V hi (post-RoPE)
__device__ __nv_bfloat16 g_l[(size_t)MROWS * 3072];   // Q|K|V lo
__device__ __nv_bfloat16 g_xh[(size_t)MROWS * 1024];
__device__ __nv_bfloat16 g_xl[(size_t)MROWS * 1024];
__device__ __nv_bfloat16 g_wh[(size_t)3072 * 1024];   // Wq|Wk|Wv stacked [n][k]
__device__ __nv_bfloat16 g_wl[(size_t)3072 * 1024];
__device__ __nv_bfloat16 g_oh[(size_t)1024 * 1024];   // Wo [n][k]
__device__ __nv_bfloat16 g_ol[(size_t)1024 * 1024];
__device__ __nv_bfloat16 g_ah[(size_t)MROWS * 1024];  // attn out hi/lo
__device__ __nv_bfloat16 g_al[(size_t)MROWS * 1024];

// ---------------- helpers ---------------------------------------------------
__device__ __forceinline__ uint32_t smem_u32(const void* p) {
    uint32_t a;
    asm("{ .reg .u64 t; cvta.to.shared.u64 t, %1; cvt.u32.u64 %0, t; }"
        : "=r"(a) : "l"(p));
    return a;
}
__device__ __forceinline__ void cp_async16(uint32_t so, const void* gp) {
    asm volatile("cp.async.cg.shared.global [%0], [%1], 16;"
                 :: "r"(so), "l"(gp) : "memory");
}
__device__ __forceinline__ void ldm4(uint32_t* r, uint32_t a) {
    asm volatile("ldmatrix.sync.aligned.m8n8.x4.shared.b16 {%0,%1,%2,%3}, [%4];"
                 : "=r"(r[0]), "=r"(r[1]), "=r"(r[2]), "=r"(r[3]) : "r"(a));
}
__device__ __forceinline__ void ldm4t(uint32_t* r, uint32_t a) {
    asm volatile("ldmatrix.sync.aligned.m8n8.x4.trans.shared.b16 {%0,%1,%2,%3}, [%4];"
                 : "=r"(r[0]), "=r"(r[1]), "=r"(r[2]), "=r"(r[3]) : "r"(a));
}
__device__ __forceinline__ void mma16816(float* c, const uint32_t* a,
                                         const uint32_t* b) {
    asm volatile(
        "mma.sync.aligned.m16n8k16.row.col.f32.bf16.bf16.f32 "
        "{%0,%1,%2,%3}, {%4,%5,%6,%7}, {%8,%9}, {%0,%1,%2,%3};"
        : "+f"(c[0]), "+f"(c[1]), "+f"(c[2]), "+f"(c[3])
        : "r"(a[0]), "r"(a[1]), "r"(a[2]), "r"(a[3]), "r"(b[0]), "r"(b[1]));
}
__device__ __forceinline__ void pack_hl(float x, float y, uint32_t& hi, uint32_t& lo) {
    __nv_bfloat16 hx = __float2bfloat16(x), hy = __float2bfloat16(y);
    __nv_bfloat16 lx = __float2bfloat16(x - __bfloat162float(hx));
    __nv_bfloat16 ly = __float2bfloat16(y - __bfloat162float(hy));
    __nv_bfloat162 hp{hx, hy}, lp{lx, ly};
    hi = *(uint32_t*)&hp; lo = *(uint32_t*)&lp;
}

// ---------------- HMMA GEMM core: CTA 128x256, warp 64x64 ------------------
// A tiles 128 rows, B tiles 256 rows; rows = 64B data + 16B pad (80B).
// Stage: Ah(10240) Al(10240) Bh(20480) Bl(20480) = 61440 B. 3 stages.
#define KCH      32
#define A_TILE_B 10240
#define B_TILE_B 20480
#define STAGE_B  61440
#define NSTAGE   3
#define GSMEM_B  (NSTAGE * STAGE_B)   // 184320

template<int MODE>   // 0 = qkv (RoPE + bf16 hi/lo out), 1 = oproj (fp32 + bias)
__device__ __forceinline__ void gemm_hmma_body(
    const __nv_bfloat16* __restrict__ Ah_, const __nv_bfloat16* __restrict__ Al_,
    const __nv_bfloat16* __restrict__ Bh_, const __nv_bfloat16* __restrict__ Bl_,
    float* __restrict__ C, const float* __restrict__ bias)
{
    extern __shared__ __align__(16) char smem[];
    const uint32_t sb = smem_u32(smem);
    const int tid = threadIdx.x, lid = tid & 31, wid = tid >> 5;
    const int wm = wid >> 2, wn = wid & 3;          // 2M x 4N warps
    const int mtile = blockIdx.x, ntile = blockIdx.y;

    const __nv_bfloat16* baseA[2] = {
        Ah_ + (size_t)mtile * 128 * 1024, Al_ + (size_t)mtile * 128 * 1024 };
    const __nv_bfloat16* baseB[2] = {
        Bh_ + (size_t)ntile * 256 * 1024, Bl_ + (size_t)ntile * 256 * 1024 };

    // per-lane ldmatrix offsets (bytes)
    const int rowA = (lid & 7) + 8 * ((lid >> 3) & 1);
    const uint32_t aoff = (uint32_t)(wm * 64 + rowA) * 80 + ((lid >> 4) & 1) * 16;
    const int nB = (lid & 7) + 8 * ((lid >> 4) & 1);
    const uint32_t boff = (uint32_t)(wn * 64 + nB) * 80 + ((lid >> 3) & 1) * 16;

    float acc[4][8][4];
    #pragma unroll
    for (int mi = 0; mi < 4; mi++)
        #pragma unroll
        for (int nj = 0; nj < 8; nj++)
            #pragma unroll
            for (int q = 0; q < 4; q++) acc[mi][nj][q] = 0.f;

    auto load_chunk = [&](int kc, int stage) {
        uint32_t st = sb + stage * STAGE_B;
        #pragma unroll
        for (int v = 0; v < 4; v++) {                 // A: 1024 granules
            int idx = v * 256 + tid;
            int t = idx >> 9, r = (idx >> 2) & 127, g = idx & 3;
            cp_async16(st + t * A_TILE_B + r * 80 + g * 16,
                       baseA[t] + (size_t)r * 1024 + kc * KCH + g * 8);
        }
        #pragma unroll
        for (int v = 0; v < 8; v++) {                 // B: 2048 granules
            int idx = v * 256 + tid;
            int t = idx >> 10, r = (idx >> 2) & 255, g = idx & 3;
            cp_async16(st + 2 * A_TILE_B + t * B_TILE_B + r * 80 + g * 16,
                       baseB[t] + (size_t)r * 1024 + kc * KCH + g * 8);
        }
    };

    load_chunk(0, 0);
    asm volatile("cp.async.commit_group;" ::: "memory");
    load_chunk(1, 1);
    asm volatile("cp.async.commit_group;" ::: "memory");

    for (int i = 0; i < 32; i++) {
        asm volatile("cp.async.wait_group 1;" ::: "memory");
        __syncthreads();
        if (i + 2 < 32) load_chunk(i + 2, (i + 2) % 3);
        asm volatile("cp.async.commit_group;" ::: "memory");

        const uint32_t st = sb + (i % 3) * STAGE_B;
        #pragma unroll
        for (int ks = 0; ks < 2; ks++) {
            uint32_t ah[4][4], al[4][4];
            #pragma unroll
            for (int mi = 0; mi < 4; mi++) {
                uint32_t a = st + mi * 1280 + ks * 32 + aoff;
                ldm4(ah[mi], a);
                ldm4(al[mi], a + A_TILE_B);
            }
            uint32_t bh[8][2], bl[8][2];
            #pragma unroll
            for (int nb = 0; nb < 4; nb++) {
                uint32_t r[4];
                uint32_t a = st + 2 * A_TILE_B + nb * 1280 + ks * 32 + boff;
                ldm4(r, a);
                bh[2 * nb][0] = r[0]; bh[2 * nb][1] = r[1];
                bh[2 * nb + 1][0] = r[2]; bh[2 * nb + 1][1] = r[3];
                ldm4(r, a + B_TILE_B);
                bl[2 * nb][0] = r[0]; bl[2 * nb][1] = r[1];
                bl[2 * nb + 1][0] = r[2]; bl[2 * nb + 1][1] = r[3];
            }
            #pragma unroll
            for (int mi = 0; mi < 4; mi++)
                #pragma unroll
                for (int nj = 0; nj < 8; nj++) {
                    mma16816(acc[mi][nj], ah[mi], bh[nj]);
                    mma16816(acc[mi][nj], ah[mi], bl[nj]);
                    mma16816(acc[mi][nj], al[mi], bh[nj]);
                }
        }
    }

    const int col0 = ntile * 256 + wn * 64 + (lid & 3) * 2;

    if (MODE == 0) {
        // RoPE for Q (ntile 0..3) and K (4..7); V (8..11) passthrough
        if (ntile < 8) {
            #pragma unroll
            for (int mi = 0; mi < 4; mi++)
                #pragma unroll
                for (int nj = 0; nj < 4; nj++)
                    #pragma unroll
                    for (int q = 0; q < 4; q++) {
                        int d = nj * 8 + (lid & 3) * 2 + (q & 1);        // 0..31
                        int t = (mtile * 128 + wm * 64 + mi * 16 + (lid >> 2)
                                 + ((q >> 1) ? 8 : 0)) & (SEQ - 1);
                        float inv = expf((float)(2 * d) * (1.0f / 64.0f)
                                         * -9.210340371976184f);
                        float sn, cs;
                        sincosf((float)t * inv, &sn, &cs);
                        float x1 = acc[mi][nj][q], x2 = acc[mi][nj + 4][q];
                        acc[mi][nj][q]     = x1 * cs - x2 * sn;
                        acc[mi][nj + 4][q] = x2 * cs + x1 * sn;
                    }
        }
        #pragma unroll
        for (int mi = 0; mi < 4; mi++) {
            size_t r = mtile * 128 + wm * 64 + mi * 16 + (lid >> 2);
            #pragma unroll
            for (int nj = 0; nj < 8; nj++) {
                int c = col0 + nj * 8;
                uint32_t hv, lv;
                pack_hl(acc[mi][nj][0], acc[mi][nj][1], hv, lv);
                *(uint32_t*)(g_h + r * 3072 + c) = hv;
                *(uint32_t*)(g_l + r * 3072 + c) = lv;
                pack_hl(acc[mi][nj][2], acc[mi][nj][3], hv, lv);
                *(uint32_t*)(g_h + (r + 8) * 3072 + c) = hv;
                *(uint32_t*)(g_l + (r + 8) * 3072 + c) = lv;
            }
        }
    } else {
        #pragma unroll
        for (int mi = 0; mi < 4; mi++) {
            size_t r = mtile * 128 + wm * 64 + mi * 16 + (lid >> 2);
            #pragma unroll
            for (int nj = 0; nj < 8; nj++) {
                int c = col0 + nj * 8;
                float b0 = bias[c], b1 = bias[c + 1];
                float2 v0{acc[mi][nj][0] + b0, acc[mi][nj][1] + b1};
                float2 v1{acc[mi][nj][2] + b0, acc[mi][nj][3] + b1};
                *(float2*)(C + r * 1024 + c)       = v0;
                *(float2*)(C + (r + 8) * 1024 + c) = v1;
            }
        }
    }
}

__global__ __launch_bounds__(256, 1) void qkv_hmma() {
    gemm_hmma_body<0>(g_xh, g_xl, g_wh, g_wl, nullptr, nullptr);
}
__global__ __launch_bounds__(256, 1) void oproj_hmma(float* __restrict__ out,
                                                     const float* __restrict__ bias) {
    gemm_hmma_body<1>(g_ah, g_al, g_oh, g_ol, out, bias);
}

// ---------------- fp32 -> bf16 hi/lo split ---------------------------------
__device__ __forceinline__ void split_one(const float* __restrict__ src,
                                          __nv_bfloat16* __restrict__ hi,
                                          __nv_bfloat16* __restrict__ lo, int i) {
    float4 v = ((const float4*)src)[i];
    uint2 hv, lv;
    pack_hl(v.x, v.y, hv.x, lv.x);
    pack_hl(v.z, v.w, hv.y, lv.y);
    ((uint2*)hi)[i] = hv;
    ((uint2*)lo)[i] = lv;
}
__global__ void split_x(const float* __restrict__ src) {
    int i = blockIdx.x * blockDim.x + threadIdx.x;
    if (i < MROWS * 1024 / 4) split_one(src, g_xh, g_xl, i);
}
__global__ void split_weights(const float* __restrict__ Wq, const float* __restrict__ Wk,
                              const float* __restrict__ Wv, const float* __restrict__ Wo) {
    int t = blockIdx.x >> 10;
    int i = (blockIdx.x & 1023) * blockDim.x + threadIdx.x;
    const float* src = (t == 0) ? Wq : (t == 1) ? Wk : (t == 2) ? Wv : Wo;
    __nv_bfloat16* hi = (t < 3) ? g_wh + (size_t)t * 1024 * 1024 : g_oh;
    __nv_bfloat16* lo = (t < 3) ? g_wl + (size_t)t * 1024 * 1024 : g_ol;
    if (i < 1024 * 1024 / 4) split_one(src, hi, lo, i);
}

// ---------------- sliding-window attention, HMMA hi/lo ----------------------
#define ASM_Q 0
#define ASM_K 16384
#define ASM_V 32768
#define SWZ(r, gd) ((r) * 128 + (((gd) ^ ((r) & 7)) * 16))

__global__ __launch_bounds__(128) void attn_kernel() {
    __shared__ __align__(16) char sm[49152];
    const uint32_t sb = smem_u32(sm);
    const int tid = threadIdx.x, lid = tid & 31, wid = tid >> 5;
    const int t0 = blockIdx.x * 64, h = blockIdx.y, b = blockIdx.z;

    {
        const size_t qr0 = (size_t)(b * SEQ + t0);
        #pragma unroll
        for (int it = 0; it < 4; it++) {
            int idx = it * 128 + tid;
            int r = idx >> 3, gd = idx & 7;
            uint32_t dst = sb + ASM_Q + SWZ(r, gd);
            cp_async16(dst,        g_h + (qr0 + r) * 3072 + h * 64 + gd * 8);
            cp_async16(dst + 8192, g_l + (qr0 + r) * 3072 + h * 64 + gd * 8);
        }
        asm volatile("cp.async.commit_group;\ncp.async.wait_group 0;" ::: "memory");
        __syncthreads();
    }
    uint32_t qh[4][4], ql[4][4];
    {
        int r = wid * 16 + (lid & 15);
        int gs = (lid >> 4) & 1;
        #pragma unroll
        for (int ks = 0; ks < 4; ks++) {
            uint32_t a = sb + ASM_Q + SWZ(r, ks * 2 + gs);
            ldm4(qh[ks], a);
            ldm4(ql[ks], a + 8192);
        }
    }

    float mmax0 = -1e30f, mmax1 = -1e30f, lsum0 = 0.f, lsum1 = 0.f;
    float o[8][4];
    #pragma unroll
    for (int nt = 0; nt < 8; nt++)
        #pragma unroll
        for (int q = 0; q < 4; q++) o[nt][q] = 0.f;

    const int qrow_a = t0 + wid * 16 + (lid >> 2);
    const int qrow_b = qrow_a + 8;

    for (int cch = 0; cch < 3; cch++) {
        const int ks0 = t0 - 128 + cch * 64;
        if (ks0 < 0) continue;

        __syncthreads();
        {
            const size_t kr0 = (size_t)(b * SEQ + ks0);
            #pragma unroll
            for (int it = 0; it < 4; it++) {
                int idx = it * 128 + tid;
                int r = idx >> 3, gd = idx & 7;
                uint32_t sw = SWZ(r, gd);
                size_t go = (kr0 + r) * 3072 + h * 64 + gd * 8;
                cp_async16(sb + ASM_K + sw,        g_h + go + 1024);
                cp_async16(sb + ASM_K + 8192 + sw, g_l + go + 1024);
                cp_async16(sb + ASM_V + sw,        g_h + go + 2048);
                cp_async16(sb + ASM_V + 8192 + sw, g_l + go + 2048);
            }
            asm volatile("cp.async.commit_group;\ncp.async.wait_group 0;" ::: "memory");
            __syncthreads();
        }

        float s[8][4];
        #pragma unroll
        for (int nt = 0; nt < 8; nt++)
            #pragma unroll
            for (int q = 0; q < 4; q++) s[nt][q] = 0.f;

        #pragma unroll
        for (int ks = 0; ks < 4; ks++) {
            const int n  = (lid & 7) + 8 * ((lid >> 4) & 1);
            const int gd = ks * 2 + ((lid >> 3) & 1);
            #pragma unroll
            for (int np = 0; np < 4; np++) {
                uint32_t kh[4], kl[4];
                int row = np * 16 + n;
                uint32_t a = sb + ASM_K + SWZ(row, gd);
                ldm4(kh, a);
                ldm4(kl, a + 8192);
                uint32_t bh0[2] = {kh[0], kh[1]}, bh1[2] = {kh[2], kh[3]};
                uint32_t bl0[2] = {kl[0], kl[1]}, bl1[2] = {kl[2], kl[3]};
                mma16816(s[2 * np],     qh[ks], bh0);
                mma16816(s[2 * np],     qh[ks], bl0);
                mma16816(s[2 * np],     ql[ks], bh0);
                mma16816(s[2 * np + 1], qh[ks], bh1);
                mma16816(s[2 * np + 1], qh[ks], bl1);
                mma16816(s[2 * np + 1], ql[ks], bh1);
            }
        }

        float mloc0 = -1e30f, mloc1 = -1e30f;
        #pragma unroll
        for (int nt = 0; nt < 8; nt++)
            #pragma unroll
            for (int e = 0; e < 2; e++) {
                int kg = ks0 + nt * 8 + (lid & 3) * 2 + e;
                float v0 = s[nt][e] * 0.125f;
                float v1 = s[nt][2 + e] * 0.125f;
                if (kg > qrow_a || kg < qrow_a - 127) v0 = -1e30f;
                if (kg > qrow_b || kg < qrow_b - 127) v1 = -1e30f;
                s[nt][e] = v0; s[nt][2 + e] = v1;
                mloc0 = fmaxf(mloc0, v0);
                mloc1 = fmaxf(mloc1, v1);
            }
        mloc0 = fmaxf(mloc0, __shfl_xor_sync(0xffffffffu, mloc0, 1));
        mloc0 = fmaxf(mloc0, __shfl_xor_sync(0xffffffffu, mloc0, 2));
        mloc1 = fmaxf(mloc1, __shfl_xor_sync(0xffffffffu, mloc1, 1));
        mloc1 = fmaxf(mloc1, __shfl_xor_sync(0xffffffffu, mloc1, 2));
        float mn0 = fmaxf(mmax0, mloc0), mn1 = fmaxf(mmax1, mloc1);
        float al0 = __expf(mmax0 - mn0), al1 = __expf(mmax1 - mn1);
        float ps0 = 0.f, ps1 = 0.f;
        #pragma unroll
        for (int nt = 0; nt < 8; nt++)
            #pragma unroll
            for (int e = 0; e < 2; e++) {
                float p0 = __expf(s[nt][e] - mn0);
                float p1 = __expf(s[nt][2 + e] - mn1);
                s[nt][e] = p0; s[nt][2 + e] = p1;
                ps0 += p0; ps1 += p1;
            }
        ps0 += __shfl_xor_sync(0xffffffffu, ps0, 1);
        ps0 += __shfl_xor_sync(0xffffffffu, ps0, 2);
        ps1 += __shfl_xor_sync(0xffffffffu, ps1, 1);
        ps1 += __shfl_xor_sync(0xffffffffu, ps1, 2);
        mmax0 = mn0; mmax1 = mn1;
        lsum0 = lsum0 * al0 + ps0;
        lsum1 = lsum1 * al1 + ps1;
        #pragma unroll
        for (int nt = 0; nt < 8; nt++) {
            o[nt][0] *= al0; o[nt][1] *= al0;
            o[nt][2] *= al1; o[nt][3] *= al1;
        }

        uint32_t ph[4][4], pl[4][4];
        #pragma unroll
        for (int ks = 0; ks < 4; ks++) {
            pack_hl(s[2 * ks][0],     s[2 * ks][1],     ph[ks][0], pl[ks][0]);
            pack_hl(s[2 * ks][2],     s[2 * ks][3],     ph[ks][1], pl[ks][1]);
            pack_hl(s[2 * ks + 1][0], s[2 * ks + 1][1], ph[ks][2], pl[ks][2]);
            pack_hl(s[2 * ks + 1][2], s[2 * ks + 1][3], ph[ks][3], pl[ks][3]);
        }

        #pragma unroll
        for (int ks = 0; ks < 4; ks++) {
            const int tile = lid >> 3;
            const int r = ks * 16 + (tile & 1) * 8 + (lid & 7);
            #pragma unroll
            for (int dp = 0; dp < 4; dp++) {
                uint32_t vh[4], vl[4];
                uint32_t a = sb + ASM_V + SWZ(r, dp * 2 + (tile >> 1));
                ldm4t(vh, a);
                ldm4t(vl, a + 8192);
                uint32_t bh0[2] = {vh[0], vh[1]}, bh1[2] = {vh[2], vh[3]};
                uint32_t bl0[2] = {vl[0], vl[1]}, bl1[2] = {vl[2], vl[3]};
                mma16816(o[2 * dp],     ph[ks], bh0);
                mma16816(o[2 * dp],     ph[ks], bl0);
                mma16816(o[2 * dp],     pl[ks], bh0);
                mma16816(o[2 * dp + 1], ph[ks], bh1);
                mma16816(o[2 * dp + 1], ph[ks], bl1);
                mma16816(o[2 * dp + 1], pl[ks], bh1);
            }
        }
    }

    const float il0 = 1.0f / lsum0, il1 = 1.0f / lsum1;
    const size_t r0 = (size_t)(b * SEQ + t0 + wid * 16 + (lid >> 2));
    const size_t r1 = r0 + 8;
    const int c0 = h * 64 + (lid & 3) * 2;
    #pragma unroll
    for (int nt = 0; nt < 8; nt++) {
        int c = c0 + nt * 8;
        uint32_t hv, lv;
        pack_hl(o[nt][0] * il0, o[nt][1] * il0, hv, lv);
        *(uint32_t*)(g_ah + r0 * 1024 + c) = hv;
        *(uint32_t*)(g_al + r0 * 1024 + c) = lv;
        pack_hl(o[nt][2] * il1, o[nt][3] * il1, hv, lv);
        *(uint32_t*)(g_ah + r1 * 1024 + c) = hv;
        *(uint32_t*)(g_al + r1 * 1024 + c) = lv;
    }
}

// ---------------------------------------------------------------------------
extern "C" void kernel_launch(void* const* d_in, const int* in_sizes, int n_in,
                              void* d_out, int out_size) {
    (void)in_sizes; (void)n_in; (void)out_size;
    const float* X  = (const float*)d_in[0];
    const float* Wq = (const float*)d_in[1];
    const float* Wk = (const float*)d_in[2];
    const float* Wv = (const float*)d_in[3];
    const float* Wo = (const float*)d_in[4];
    const float* bo = (const float*)d_in[5];
    float* out = (float*)d_out;

    cudaFuncSetAttribute(qkv_hmma,   cudaFuncAttributeMaxDynamicSharedMemorySize, GSMEM_B);
    cudaFuncSetAttribute(oproj_hmma, cudaFuncAttributeMaxDynamicSharedMemorySize, GSMEM_B);

    split_x<<<4096, 256>>>(X);
    split_weights<<<4096, 256>>>(Wq, Wk, Wv, Wo);

    qkv_hmma<<<dim3(32, 12), 256, GSMEM_B>>>();
    attn_kernel<<<dim3(SEQ / 64, NH, NB), 128>>>();
    oproj_hmma<<<dim3(32, 4), 256, GSMEM_B>>>(out, bo);
}

// round 13
// speedup vs baseline: 3.8411x; 1.3955x over previous
#include <cuda_runtime.h>
#include <cuda_fp16.h>
#include <cstdint>
#include <cstddef>

#define D_MODEL 1024
#define SEQ     2048
#define NB      2
#define NH      16
#define MROWS   4096   // NB * SEQ

// ---------------- scratch (device globals only — no allocs allowed) --------
__device__ __half g_h[(size_t)MROWS * 3072];   // Q|K|V hi (post-RoPE)
__device__ __half g_l[(size_t)MROWS * 3072];   // Q lo (K/V lo unused)
__device__ __half g_xh[(size_t)MROWS * 1024];
__device__ __half g_xl[(size_t)MROWS * 1024];
__device__ __half g_wh[(size_t)3072 * 1024];   // Wq|Wk|Wv stacked [n][k], hi only
__device__ __half g_oh[(size_t)1024 * 1024];   // Wo [n][k], hi only
__device__ __half g_ah[(size_t)MROWS * 1024];  // attn out hi/lo
__device__ __half g_al[(size_t)MROWS * 1024];

// ---------------- helpers ---------------------------------------------------
__device__ __forceinline__ uint32_t smem_u32(const void* p) {
    uint32_t a;
    asm("{ .reg .u64 t; cvta.to.shared.u64 t, %1; cvt.u32.u64 %0, t; }"
        : "=r"(a) : "l"(p));
    return a;
}
__device__ __forceinline__ void cp_async16(uint32_t so, const void* gp) {
    asm volatile("cp.async.cg.shared.global [%0], [%1], 16;"
                 :: "r"(so), "l"(gp) : "memory");
}
__device__ __forceinline__ void ldm4(uint32_t* r, uint32_t a) {
    asm volatile("ldmatrix.sync.aligned.m8n8.x4.shared.b16 {%0,%1,%2,%3}, [%4];"
                 : "=r"(r[0]), "=r"(r[1]), "=r"(r[2]), "=r"(r[3]) : "r"(a));
}
__device__ __forceinline__ void ldm4t(uint32_t* r, uint32_t a) {
    asm volatile("ldmatrix.sync.aligned.m8n8.x4.trans.shared.b16 {%0,%1,%2,%3}, [%4];"
                 : "=r"(r[0]), "=r"(r[1]), "=r"(r[2]), "=r"(r[3]) : "r"(a));
}
__device__ __forceinline__ void mma16816(float* c, const uint32_t* a,
                                         const uint32_t* b) {
    asm volatile(
        "mma.sync.aligned.m16n8k16.row.col.f32.f16.f16.f32 "
        "{%0,%1,%2,%3}, {%4,%5,%6,%7}, {%8,%9}, {%0,%1,%2,%3};"
        : "+f"(c[0]), "+f"(c[1]), "+f"(c[2]), "+f"(c[3])
        : "r"(a[0]), "r"(a[1]), "r"(a[2]), "r"(a[3]), "r"(b[0]), "r"(b[1]));
}
__device__ __forceinline__ void pack_hl(float x, float y, uint32_t& hi, uint32_t& lo) {
    __half hx = __float2half(x), hy = __float2half(y);
    __half lx = __float2half(x - __half2float(hx));
    __half ly = __float2half(y - __half2float(hy));
    __half2 hp{hx, hy}, lp{lx, ly};
    hi = *(uint32_t*)&hp; lo = *(uint32_t*)&lp;
}
__device__ __forceinline__ uint32_t pack_h(float x, float y) {
    __half2 hp{__float2half(x), __float2half(y)};
    return *(uint32_t*)&hp;
}

// ---------------- HMMA GEMM core: CTA 128x256, warp 64x64, 2-term fp16 -----
// Stage: Ah(10240) Al(10240) Bh(20480) = 40960 B. 4 stages.
#define KCH      32
#define A_TILE_B 10240
#define B_TILE_B 20480
#define STAGE_B  40960
#define NSTAGE   4
#define GSMEM_B  (NSTAGE * STAGE_B)   // 163840

template<int MODE>   // 0 = qkv (RoPE + fp16 hi/lo out), 1 = oproj (fp32 + bias)
__device__ __forceinline__ void gemm_hmma_body(
    const __half* __restrict__ Ah_, const __half* __restrict__ Al_,
    const __half* __restrict__ Bh_,
    float* __restrict__ C, const float* __restrict__ bias)
{
    extern __shared__ __align__(16) char smem[];
    const uint32_t sb = smem_u32(smem);
    const int tid = threadIdx.x, lid = tid & 31, wid = tid >> 5;
    const int wm = wid >> 2, wn = wid & 3;          // 2M x 4N warps
    const int mtile = blockIdx.x, ntile = blockIdx.y;

    const __half* baseA[2] = {
        Ah_ + (size_t)mtile * 128 * 1024, Al_ + (size_t)mtile * 128 * 1024 };
    const __half* baseB = Bh_ + (size_t)ntile * 256 * 1024;

    const int rowA = (lid & 7) + 8 * ((lid >> 3) & 1);
    const uint32_t aoff = (uint32_t)(wm * 64 + rowA) * 80 + ((lid >> 4) & 1) * 16;
    const int nB = (lid & 7) + 8 * ((lid >> 4) & 1);
    const uint32_t boff = (uint32_t)(wn * 64 + nB) * 80 + ((lid >> 3) & 1) * 16;

    float acc[4][8][4];
    #pragma unroll
    for (int mi = 0; mi < 4; mi++)
        #pragma unroll
        for (int nj = 0; nj < 8; nj++)
            #pragma unroll
            for (int q = 0; q < 4; q++) acc[mi][nj][q] = 0.f;

    auto load_chunk = [&](int kc, int stage) {
        uint32_t st = sb + stage * STAGE_B;
        #pragma unroll
        for (int v = 0; v < 4; v++) {                 // A: hi+lo, 1024 granules
            int idx = v * 256 + tid;
            int t = idx >> 9, r = (idx >> 2) & 127, g = idx & 3;
            cp_async16(st + t * A_TILE_B + r * 80 + g * 16,
                       baseA[t] + (size_t)r * 1024 + kc * KCH + g * 8);
        }
        #pragma unroll
        for (int v = 0; v < 4; v++) {                 // B: hi only, 1024 granules
            int idx = v * 256 + tid;
            int r = (idx >> 2) & 255, g = idx & 3;
            cp_async16(st + 2 * A_TILE_B + r * 80 + g * 16,
                       baseB + (size_t)r * 1024 + kc * KCH + g * 8);
        }
    };

    load_chunk(0, 0);
    asm volatile("cp.async.commit_group;" ::: "memory");
    load_chunk(1, 1);
    asm volatile("cp.async.commit_group;" ::: "memory");
    load_chunk(2, 2);
    asm volatile("cp.async.commit_group;" ::: "memory");

    for (int i = 0; i < 32; i++) {
        asm volatile("cp.async.wait_group 2;" ::: "memory");
        __syncthreads();
        if (i + 3 < 32) load_chunk(i + 3, (i + 3) & 3);
        asm volatile("cp.async.commit_group;" ::: "memory");

        const uint32_t st = sb + (i & 3) * STAGE_B;
        #pragma unroll
        for (int ks = 0; ks < 2; ks++) {
            uint32_t ah[4][4], al[4][4];
            #pragma unroll
            for (int mi = 0; mi < 4; mi++) {
                uint32_t a = st + mi * 1280 + ks * 32 + aoff;
                ldm4(ah[mi], a);
                ldm4(al[mi], a + A_TILE_B);
            }
            uint32_t bh[8][2];
            #pragma unroll
            for (int nb = 0; nb < 4; nb++) {
                uint32_t r[4];
                ldm4(r, st + 2 * A_TILE_B + nb * 1280 + ks * 32 + boff);
                bh[2 * nb][0] = r[0]; bh[2 * nb][1] = r[1];
                bh[2 * nb + 1][0] = r[2]; bh[2 * nb + 1][1] = r[3];
            }
            #pragma unroll
            for (int mi = 0; mi < 4; mi++)
                #pragma unroll
                for (int nj = 0; nj < 8; nj++) {
                    mma16816(acc[mi][nj], ah[mi], bh[nj]);
                    mma16816(acc[mi][nj], al[mi], bh[nj]);
                }
        }
    }

    const int col0 = ntile * 256 + wn * 64 + (lid & 3) * 2;

    if (MODE == 0) {
        // RoPE for Q (ntile 0..3) and K (4..7); V (8..11) passthrough
        if (ntile < 8) {
            #pragma unroll
            for (int mi = 0; mi < 4; mi++)
                #pragma unroll
                for (int nj = 0; nj < 4; nj++)
                    #pragma unroll
                    for (int q = 0; q < 4; q++) {
                        int d = nj * 8 + (lid & 3) * 2 + (q & 1);        // 0..31
                        int t = (mtile * 128 + wm * 64 + mi * 16 + (lid >> 2)
                                 + ((q >> 1) ? 8 : 0)) & (SEQ - 1);
                        float inv = expf((float)(2 * d) * (1.0f / 64.0f)
                                         * -9.210340371976184f);
                        float sn, cs;
                        sincosf((float)t * inv, &sn, &cs);
                        float x1 = acc[mi][nj][q], x2 = acc[mi][nj + 4][q];
                        acc[mi][nj][q]     = x1 * cs - x2 * sn;
                        acc[mi][nj + 4][q] = x2 * cs + x1 * sn;
                    }
        }
        const bool needLo = (ntile < 4);    // only Q is an A-side operand later
        #pragma unroll
        for (int mi = 0; mi < 4; mi++) {
            size_t r = mtile * 128 + wm * 64 + mi * 16 + (lid >> 2);
            #pragma unroll
            for (int nj = 0; nj < 8; nj++) {
                int c = col0 + nj * 8;
                if (needLo) {
                    uint32_t hv, lv;
                    pack_hl(acc[mi][nj][0], acc[mi][nj][1], hv, lv);
                    *(uint32_t*)(g_h + r * 3072 + c) = hv;
                    *(uint32_t*)(g_l + r * 3072 + c) = lv;
                    pack_hl(acc[mi][nj][2], acc[mi][nj][3], hv, lv);
                    *(uint32_t*)(g_h + (r + 8) * 3072 + c) = hv;
                    *(uint32_t*)(g_l + (r + 8) * 3072 + c) = lv;
                } else {
                    *(uint32_t*)(g_h + r * 3072 + c) =
                        pack_h(acc[mi][nj][0], acc[mi][nj][1]);
                    *(uint32_t*)(g_h + (r + 8) * 3072 + c) =
                        pack_h(acc[mi][nj][2], acc[mi][nj][3]);
                }
            }
        }
    } else {
        #pragma unroll
        for (int mi = 0; mi < 4; mi++) {
            size_t r = mtile * 128 + wm * 64 + mi * 16 + (lid >> 2);
            #pragma unroll
            for (int nj = 0; nj < 8; nj++) {
                int c = col0 + nj * 8;
                float b0 = bias[c], b1 = bias[c + 1];
                float2 v0{acc[mi][nj][0] + b0, acc[mi][nj][1] + b1};
                float2 v1{acc[mi][nj][2] + b0, acc[mi][nj][3] + b1};
                *(float2*)(C + r * 1024 + c)       = v0;
                *(float2*)(C + (r + 8) * 1024 + c) = v1;
            }
        }
    }
}

__global__ __launch_bounds__(256, 1) void qkv_hmma() {
    gemm_hmma_body<0>(g_xh, g_xl, g_wh, nullptr, nullptr);
}
__global__ __launch_bounds__(256, 1) void oproj_hmma(float* __restrict__ out,
                                                     const float* __restrict__ bias) {
    gemm_hmma_body<1>(g_ah, g_al, g_oh, out, bias);
}

// ---------------- fp32 -> fp16 conversion kernels ---------------------------
__global__ void split_x(const float* __restrict__ src) {
    int i = blockIdx.x * blockDim.x + threadIdx.x;
    if (i >= MROWS * 1024 / 4) return;
    float4 v = ((const float4*)src)[i];
    uint2 hv, lv;
    pack_hl(v.x, v.y, hv.x, lv.x);
    pack_hl(v.z, v.w, hv.y, lv.y);
    ((uint2*)g_xh)[i] = hv;
    ((uint2*)g_xl)[i] = lv;
}
__global__ void conv_w(const float* __restrict__ Wq, const float* __restrict__ Wk,
                       const float* __restrict__ Wv, const float* __restrict__ Wo) {
    int t = blockIdx.x >> 10;
    int i = (blockIdx.x & 1023) * blockDim.x + threadIdx.x;
    if (i >= 1024 * 1024 / 4) return;
    const float* src = (t == 0) ? Wq : (t == 1) ? Wk : (t == 2) ? Wv : Wo;
    __half* dst = (t < 3) ? g_wh + (size_t)t * 1024 * 1024 : g_oh;
    float4 v = ((const float4*)src)[i];
    uint2 hv{pack_h(v.x, v.y), pack_h(v.z, v.w)};
    ((uint2*)dst)[i] = hv;
}

// ---------------- sliding-window attention, HMMA fp16 2-term ----------------
// smem: Q hi 8KB | Q lo 8KB | K hi 8KB | V hi 8KB = 32KB.
#define ASM_QH 0
#define ASM_QL 8192
#define ASM_K  16384
#define ASM_V  24576
#define SWZ(r, gd) ((r) * 128 + (((gd) ^ ((r) & 7)) * 16))

__global__ __launch_bounds__(128) void attn_kernel() {
    __shared__ __align__(16) char sm[32768];
    const uint32_t sb = smem_u32(sm);
    const int tid = threadIdx.x, lid = tid & 31, wid = tid >> 5;
    const int t0 = blockIdx.x * 64, h = blockIdx.y, b = blockIdx.z;

    {
        const size_t qr0 = (size_t)(b * SEQ + t0);
        #pragma unroll
        for (int it = 0; it < 4; it++) {
            int idx = it * 128 + tid;
            int r = idx >> 3, gd = idx & 7;
            uint32_t sw = SWZ(r, gd);
            size_t go = (qr0 + r) * 3072 + h * 64 + gd * 8;
            cp_async16(sb + ASM_QH + sw, g_h + go);
            cp_async16(sb + ASM_QL + sw, g_l + go);
        }
        asm volatile("cp.async.commit_group;\ncp.async.wait_group 0;" ::: "memory");
        __syncthreads();
    }
    uint32_t qh[4][4], ql[4][4];
    {
        int r = wid * 16 + (lid & 15);
        int gs = (lid >> 4) & 1;
        #pragma unroll
        for (int ks = 0; ks < 4; ks++) {
            uint32_t sw = SWZ(r, ks * 2 + gs);
            ldm4(qh[ks], sb + ASM_QH + sw);
            ldm4(ql[ks], sb + ASM_QL + sw);
        }
    }

    float mmax0 = -1e30f, mmax1 = -1e30f, lsum0 = 0.f, lsum1 = 0.f;
    float o[8][4];
    #pragma unroll
    for (int nt = 0; nt < 8; nt++)
        #pragma unroll
        for (int q = 0; q < 4; q++) o[nt][q] = 0.f;

    const int qrow_a = t0 + wid * 16 + (lid >> 2);
    const int qrow_b = qrow_a + 8;

    for (int cch = 0; cch < 3; cch++) {
        const int ks0 = t0 - 128 + cch * 64;
        if (ks0 < 0) continue;

        __syncthreads();
        {
            const size_t kr0 = (size_t)(b * SEQ + ks0);
            #pragma unroll
            for (int it = 0; it < 4; it++) {
                int idx = it * 128 + tid;
                int r = idx >> 3, gd = idx & 7;
                uint32_t sw = SWZ(r, gd);
                size_t go = (kr0 + r) * 3072 + h * 64 + gd * 8;
                cp_async16(sb + ASM_K + sw, g_h + go + 1024);
                cp_async16(sb + ASM_V + sw, g_h + go + 2048);
            }
            asm volatile("cp.async.commit_group;\ncp.async.wait_group 0;" ::: "memory");
            __syncthreads();
        }

        float s[8][4];
        #pragma unroll
        for (int nt = 0; nt < 8; nt++)
            #pragma unroll
            for (int q = 0; q < 4; q++) s[nt][q] = 0.f;

        #pragma unroll
        for (int ks = 0; ks < 4; ks++) {
            const int n  = (lid & 7) + 8 * ((lid >> 4) & 1);
            const int gd = ks * 2 + ((lid >> 3) & 1);
            #pragma unroll
            for (int np = 0; np < 4; np++) {
                uint32_t kh[4];
                int row = np * 16 + n;
                ldm4(kh, sb + ASM_K + SWZ(row, gd));
                uint32_t bh0[2] = {kh[0], kh[1]}, bh1[2] = {kh[2], kh[3]};
                mma16816(s[2 * np],     qh[ks], bh0);
                mma16816(s[2 * np],     ql[ks], bh0);
                mma16816(s[2 * np + 1], qh[ks], bh1);
                mma16816(s[2 * np + 1], ql[ks], bh1);
            }
        }

        float mloc0 = -1e30f, mloc1 = -1e30f;
        #pragma unroll
        for (int nt = 0; nt < 8; nt++)
            #pragma unroll
            for (int e = 0; e < 2; e++) {
                int kg = ks0 + nt * 8 + (lid & 3) * 2 + e;
                float v0 = s[nt][e] * 0.125f;
                float v1 = s[nt][2 + e] * 0.125f;
                if (kg > qrow_a || kg < qrow_a - 127) v0 = -1e30f;
                if (kg > qrow_b || kg < qrow_b - 127) v1 = -1e30f;
                s[nt][e] = v0; s[nt][2 + e] = v1;
                mloc0 = fmaxf(mloc0, v0);
                mloc1 = fmaxf(mloc1, v1);
            }
        mloc0 = fmaxf(mloc0, __shfl_xor_sync(0xffffffffu, mloc0, 1));
        mloc0 = fmaxf(mloc0, __shfl_xor_sync(0xffffffffu, mloc0, 2));
        mloc1 = fmaxf(mloc1, __shfl_xor_sync(0xffffffffu, mloc1, 1));
        mloc1 = fmaxf(mloc1, __shfl_xor_sync(0xffffffffu, mloc1, 2));
        float mn0 = fmaxf(mmax0, mloc0), mn1 = fmaxf(mmax1, mloc1);
        float al0 = __expf(mmax0 - mn0), al1 = __expf(mmax1 - mn1);
        float ps0 = 0.f, ps1 = 0.f;
        #pragma unroll
        for (int nt = 0; nt < 8; nt++)
            #pragma unroll
            for (int e = 0; e < 2; e++) {
                float p0 = __expf(s[nt][e] - mn0);
                float p1 = __expf(s[nt][2 + e] - mn1);
                s[nt][e] = p0; s[nt][2 + e] = p1;
                ps0 += p0; ps1 += p1;
            }
        ps0 += __shfl_xor_sync(0xffffffffu, ps0, 1);
        ps0 += __shfl_xor_sync(0xffffffffu, ps0, 2);
        ps1 += __shfl_xor_sync(0xffffffffu, ps1, 1);
        ps1 += __shfl_xor_sync(0xffffffffu, ps1, 2);
        mmax0 = mn0; mmax1 = mn1;
        lsum0 = lsum0 * al0 + ps0;
        lsum1 = lsum1 * al1 + ps1;
        #pragma unroll
        for (int nt = 0; nt < 8; nt++) {
            o[nt][0] *= al0; o[nt][1] *= al0;
            o[nt][2] *= al1; o[nt][3] *= al1;
        }

        uint32_t ph[4][4], pl[4][4];
        #pragma unroll
        for (int ks = 0; ks < 4; ks++) {
            pack_hl(s[2 * ks][0],     s[2 * ks][1],     ph[ks][0], pl[ks][0]);
            pack_hl(s[2 * ks][2],     s[2 * ks][3],     ph[ks][1], pl[ks][1]);
            pack_hl(s[2 * ks + 1][0], s[2 * ks + 1][1], ph[ks][2], pl[ks][2]);
            pack_hl(s[2 * ks + 1][2], s[2 * ks + 1][3], ph[ks][3], pl[ks][3]);
        }

        #pragma unroll
        for (int ks = 0; ks < 4; ks++) {
            const int tile = lid >> 3;
            const int r = ks * 16 + (tile & 1) * 8 + (lid & 7);
            #pragma unroll
            for (int dp = 0; dp < 4; dp++) {
                uint32_t vh[4];
                ldm4t(vh, sb + ASM_V + SWZ(r, dp * 2 + (tile >> 1)));
                uint32_t bh0[2] = {vh[0], vh[1]}, bh1[2] = {vh[2], vh[3]};
                mma16816(o[2 * dp],     ph[ks], bh0);
                mma16816(o[2 * dp],     pl[ks], bh0);
                mma16816(o[2 * dp + 1], ph[ks], bh1);
                mma16816(o[2 * dp + 1], pl[ks], bh1);
            }
        }
    }

    const float il0 = 1.0f / lsum0, il1 = 1.0f / lsum1;
    const size_t r0 = (size_t)(b * SEQ + t0 + wid * 16 + (lid >> 2));
    const size_t r1 = r0 + 8;
    const int c0 = h * 64 + (lid & 3) * 2;
    #pragma unroll
    for (int nt = 0; nt < 8; nt++) {
        int c = c0 + nt * 8;
        uint32_t hv, lv;
        pack_hl(o[nt][0] * il0, o[nt][1] * il0, hv, lv);
        *(uint32_t*)(g_ah + r0 * 1024 + c) = hv;
        *(uint32_t*)(g_al + r0 * 1024 + c) = lv;
        pack_hl(o[nt][2] * il1, o[nt][3] * il1, hv, lv);
        *(uint32_t*)(g_ah + r1 * 1024 + c) = hv;
        *(uint32_t*)(g_al + r1 * 1024 + c) = lv;
    }
}

// ---------------------------------------------------------------------------
extern "C" void kernel_launch(void* const* d_in, const int* in_sizes, int n_in,
                              void* d_out, int out_size) {
    (void)in_sizes; (void)n_in; (void)out_size;
    const float* X  = (const float*)d_in[0];
    const float* Wq = (const float*)d_in[1];
    const float* Wk = (const float*)d_in[2];
    const float* Wv = (const float*)d_in[3];
    const float* Wo = (const float*)d_in[4];
    const float* bo = (const float*)d_in[5];
    float* out = (float*)d_out;

    cudaFuncSetAttribute(qkv_hmma,   cudaFuncAttributeMaxDynamicSharedMemorySize, GSMEM_B);
    cudaFuncSetAttribute(oproj_hmma, cudaFuncAttributeMaxDynamicSharedMemorySize, GSMEM_B);

    split_x<<<4096, 256>>>(X);
    conv_w<<<4096, 256>>>(Wq, Wk, Wv, Wo);

    qkv_hmma<<<dim3(32, 12), 256, GSMEM_B>>>();
    attn_kernel<<<dim3(SEQ / 64, NH, NB), 128>>>();
    oproj_hmma<<<dim3(32, 4), 256, GSMEM_B>>>(out, bo);
}

// round 15
// speedup vs baseline: 4.1286x; 1.0749x over previous
#include <cuda_runtime.h>
#include <cuda_fp16.h>
#include <cstdint>
#include <cstddef>

#define D_MODEL 1024
#define SEQ     2048
#define NB      2
#define NH      16
#define MROWS   4096   // NB * SEQ

// ---------------- scratch (device globals only — no allocs allowed) --------
__device__ __half g_h[(size_t)MROWS * 3072];   // Q|K|V hi (post-RoPE)
__device__ __half g_l[(size_t)MROWS * 3072];   // Q lo (K/V lo unused)
__device__ __half g_xh[(size_t)MROWS * 1024];
__device__ __half g_xl[(size_t)MROWS * 1024];
__device__ __half g_wh[(size_t)3072 * 1024];   // Wq|Wk|Wv stacked [n][k], hi only
__device__ __half g_oh[(size_t)1024 * 1024];   // Wo [n][k], hi only
__device__ __half g_ah[(size_t)MROWS * 1024];  // attn out hi/lo
__device__ __half g_al[(size_t)MROWS * 1024];

// ---------------- helpers ---------------------------------------------------
__device__ __forceinline__ uint32_t smem_u32(const void* p) {
    uint32_t a;
    asm("{ .reg .u64 t; cvta.to.shared.u64 t, %1; cvt.u32.u64 %0, t; }"
        : "=r"(a) : "l"(p));
    return a;
}
__device__ __forceinline__ void cp_async16(uint32_t so, const void* gp) {
    asm volatile("cp.async.cg.shared.global [%0], [%1], 16;"
                 :: "r"(so), "l"(gp) : "memory");
}
__device__ __forceinline__ void ldm4(uint32_t* r, uint32_t a) {
    asm volatile("ldmatrix.sync.aligned.m8n8.x4.shared.b16 {%0,%1,%2,%3}, [%4];"
                 : "=r"(r[0]), "=r"(r[1]), "=r"(r[2]), "=r"(r[3]) : "r"(a));
}
__device__ __forceinline__ void ldm4t(uint32_t* r, uint32_t a) {
    asm volatile("ldmatrix.sync.aligned.m8n8.x4.trans.shared.b16 {%0,%1,%2,%3}, [%4];"
                 : "=r"(r[0]), "=r"(r[1]), "=r"(r[2]), "=r"(r[3]) : "r"(a));
}
__device__ __forceinline__ void mma16816(float* c, const uint32_t* a,
                                         const uint32_t* b) {
    asm volatile(
        "mma.sync.aligned.m16n8k16.row.col.f32.f16.f16.f32 "
        "{%0,%1,%2,%3}, {%4,%5,%6,%7}, {%8,%9}, {%0,%1,%2,%3};"
        : "+f"(c[0]), "+f"(c[1]), "+f"(c[2]), "+f"(c[3])
        : "r"(a[0]), "r"(a[1]), "r"(a[2]), "r"(a[3]), "r"(b[0]), "r"(b[1]));
}
__device__ __forceinline__ void pack_hl(float x, float y, uint32_t& hi, uint32_t& lo) {
    __half hx = __float2half(x), hy = __float2half(y);
    __half lx = __float2half(x - __half2float(hx));
    __half ly = __float2half(y - __half2float(hy));
    __half2 hp{hx, hy}, lp{lx, ly};
    hi = *(uint32_t*)&hp; lo = *(uint32_t*)&lp;
}
__device__ __forceinline__ uint32_t pack_h(float x, float y) {
    __half2 hp{__float2half(x), __float2half(y)};
    return *(uint32_t*)&hp;
}

// ---------------- HMMA GEMM: persistent CTAs, CTA tile 128x256 -------------
// 2-term fp16 (A split hi/lo, B hi only). K-chunk 64 (128B rows + 16B pad).
// 2-stage double buffer; flat chunk stream across tiles (no drain at tile
// boundaries); grid 128 CTAs, tiles decoded m = t&31, n = t>>5.
#define KCH2     64
#define AROW_B   144
#define A_TILE_B (128 * AROW_B)                 // 18432
#define B_TILE_B (256 * AROW_B)                 // 36864
#define STAGE_B  (2 * A_TILE_B + B_TILE_B)      // 73728
#define GSMEM_B  (2 * STAGE_B)                  // 147456
#define GRIDX    128

template<int MODE, int NT>   // MODE: 0=qkv(RoPE+fp16 out), 1=oproj(fp32+bias); NT tiles/CTA
__device__ __forceinline__ void gemm_hmma_body(
    const __half* __restrict__ Ah_, const __half* __restrict__ Al_,
    const __half* __restrict__ Bh_,
    float* __restrict__ C, const float* __restrict__ bias)
{
    extern __shared__ __align__(16) char smem[];
    const uint32_t sb = smem_u32(smem);
    const int tid = threadIdx.x, lid = tid & 31, wid = tid >> 5;
    const int wm = wid >> 2, wn = wid & 3;          // 2M x 4N warps

    const int rowA = (lid & 7) + 8 * ((lid >> 3) & 1);
    const uint32_t aoff = (uint32_t)(wm * 64 + rowA) * AROW_B + ((lid >> 4) & 1) * 16;
    const int nB = (lid & 7) + 8 * ((lid >> 4) & 1);
    const uint32_t boff = (uint32_t)(wn * 64 + nB) * AROW_B + ((lid >> 3) & 1) * 16;

    auto load_chunk = [&](int tile, int kc, int stage) {
        const int m = tile & 31, n = tile >> 5;
        const __half* A0 = Ah_ + (size_t)m * 128 * 1024;
        const __half* A1 = Al_ + (size_t)m * 128 * 1024;
        const __half* B  = Bh_ + (size_t)n * 256 * 1024;
        uint32_t st = sb + stage * STAGE_B;
        #pragma unroll
        for (int v = 0; v < 8; v++) {                 // A hi+lo: 2048 granules
            int idx = v * 256 + tid;
            int t2 = idx >> 10, r = (idx >> 3) & 127, g = idx & 7;
            const __half* src = t2 ? A1 : A0;
            cp_async16(st + t2 * A_TILE_B + r * AROW_B + g * 16,
                       src + (size_t)r * 1024 + kc * KCH2 + g * 8);
        }
        #pragma unroll
        for (int v = 0; v < 8; v++) {                 // B hi: 2048 granules
            int idx = v * 256 + tid;
            int r = (idx >> 3) & 255, g = idx & 7;
            cp_async16(st + 2 * A_TILE_B + r * AROW_B + g * 16,
                       B + (size_t)r * 1024 + kc * KCH2 + g * 8);
        }
        asm volatile("cp.async.commit_group;" ::: "memory");
    };

    const int total_chunks = NT * 16;
    load_chunk(blockIdx.x, 0, 0);
    asm volatile("cp.async.wait_group 0;" ::: "memory");
    __syncthreads();

    for (int tt = 0; tt < NT; tt++) {
        const int tile = blockIdx.x + tt * GRIDX;
        const int mtile = tile & 31, ntile = tile >> 5;

        float acc[4][8][4];
        #pragma unroll
        for (int mi = 0; mi < 4; mi++)
            #pragma unroll
            for (int nj = 0; nj < 8; nj++)
                #pragma unroll
                for (int q = 0; q < 4; q++) acc[mi][nj][q] = 0.f;

        #pragma unroll 1
        for (int i = 0; i < 16; i++) {
            const int c = tt * 16 + i;
            if (c + 1 < total_chunks)
                load_chunk(blockIdx.x + ((c + 1) >> 4) * GRIDX,
                           (c + 1) & 15, (c + 1) & 1);

            const uint32_t st = sb + (c & 1) * STAGE_B;
            #pragma unroll
            for (int ks = 0; ks < 4; ks++) {
                uint32_t ah[4][4], al[4][4];
                #pragma unroll
                for (int mi = 0; mi < 4; mi++) {
                    uint32_t a = st + mi * (16 * AROW_B) + ks * 32 + aoff;
                    ldm4(ah[mi], a);
                    ldm4(al[mi], a + A_TILE_B);
                }
                uint32_t bh[8][2];
                #pragma unroll
                for (int nb = 0; nb < 4; nb++) {
                    uint32_t r[4];
                    ldm4(r, st + 2 * A_TILE_B + nb * (16 * AROW_B) + ks * 32 + boff);
                    bh[2 * nb][0] = r[0]; bh[2 * nb][1] = r[1];
                    bh[2 * nb + 1][0] = r[2]; bh[2 * nb + 1][1] = r[3];
                }
                #pragma unroll
                for (int mi = 0; mi < 4; mi++)
                    #pragma unroll
                    for (int nj = 0; nj < 8; nj++) {
                        mma16816(acc[mi][nj], ah[mi], bh[nj]);
                        mma16816(acc[mi][nj], al[mi], bh[nj]);
                    }
            }
            asm volatile("cp.async.wait_group 0;" ::: "memory");
            __syncthreads();   // chunk c+1 visible & all warps done with chunk c
        }

        const int col0 = ntile * 256 + wn * 64 + (lid & 3) * 2;
        if (MODE == 0) {
            // RoPE for Q (ntile 0..3) and K (4..7); V (8..11) passthrough
            if (ntile < 8) {
                #pragma unroll
                for (int mi = 0; mi < 4; mi++)
                    #pragma unroll
                    for (int nj = 0; nj < 4; nj++)
                        #pragma unroll
                        for (int q = 0; q < 4; q++) {
                            int d = nj * 8 + (lid & 3) * 2 + (q & 1);    // 0..31
                            int t = (mtile * 128 + wm * 64 + mi * 16 + (lid >> 2)
                                     + ((q >> 1) ? 8 : 0)) & (SEQ - 1);
                            float inv = expf((float)(2 * d) * (1.0f / 64.0f)
                                             * -9.210340371976184f);
                            float sn, cs;
                            sincosf((float)t * inv, &sn, &cs);
                            float x1 = acc[mi][nj][q], x2 = acc[mi][nj + 4][q];
                            acc[mi][nj][q]     = x1 * cs - x2 * sn;
                            acc[mi][nj + 4][q] = x2 * cs + x1 * sn;
                        }
            }
            const bool needLo = (ntile < 4);   // only Q is an A-side operand later
            #pragma unroll
            for (int mi = 0; mi < 4; mi++) {
                size_t r = mtile * 128 + wm * 64 + mi * 16 + (lid >> 2);
                #pragma unroll
                for (int nj = 0; nj < 8; nj++) {
                    int c = col0 + nj * 8;
                    if (needLo) {
                        uint32_t hv, lv;
                        pack_hl(acc[mi][nj][0], acc[mi][nj][1], hv, lv);
                        *(uint32_t*)(g_h + r * 3072 + c) = hv;
                        *(uint32_t*)(g_l + r * 3072 + c) = lv;
                        pack_hl(acc[mi][nj][2], acc[mi][nj][3], hv, lv);
                        *(uint32_t*)(g_h + (r + 8) * 3072 + c) = hv;
                        *(uint32_t*)(g_l + (r + 8) * 3072 + c) = lv;
                    } else {
                        *(uint32_t*)(g_h + r * 3072 + c) =
                            pack_h(acc[mi][nj][0], acc[mi][nj][1]);
                        *(uint32_t*)(g_h + (r + 8) * 3072 + c) =
                            pack_h(acc[mi][nj][2], acc[mi][nj][3]);
                    }
                }
            }
        } else {
            #pragma unroll
            for (int mi = 0; mi < 4; mi++) {
                size_t r = mtile * 128 + wm * 64 + mi * 16 + (lid >> 2);
                #pragma unroll
                for (int nj = 0; nj < 8; nj++) {
                    int c = col0 + nj * 8;
                    float b0 = bias[c], b1 = bias[c + 1];
                    float2 v0{acc[mi][nj][0] + b0, acc[mi][nj][1] + b1};
                    float2 v1{acc[mi][nj][2] + b0, acc[mi][nj][3] + b1};
                    *(float2*)(C + r * 1024 + c)       = v0;
                    *(float2*)(C + (r + 8) * 1024 + c) = v1;
                }
            }
        }
    }
}

__global__ __launch_bounds__(256, 1) void qkv_hmma() {
    gemm_hmma_body<0, 3>(g_xh, g_xl, g_wh, nullptr, nullptr);
}
__global__ __launch_bounds__(256, 1) void oproj_hmma(float* __restrict__ out,
                                                     const float* __restrict__ bias) {
    gemm_hmma_body<1, 1>(g_ah, g_al, g_oh, out, bias);
}

// ---------------- fp32 -> fp16 conversion kernels ---------------------------
__global__ void split_x(const float* __restrict__ src) {
    int i = blockIdx.x * blockDim.x + threadIdx.x;
    if (i >= MROWS * 1024 / 4) return;
    float4 v = ((const float4*)src)[i];
    uint2 hv, lv;
    pack_hl(v.x, v.y, hv.x, lv.x);
    pack_hl(v.z, v.w, hv.y, lv.y);
    ((uint2*)g_xh)[i] = hv;
    ((uint2*)g_xl)[i] = lv;
}
__global__ void conv_w(const float* __restrict__ Wq, const float* __restrict__ Wk,
                       const float* __restrict__ Wv, const float* __restrict__ Wo) {
    int t = blockIdx.x >> 10;
    int i = (blockIdx.x & 1023) * blockDim.x + threadIdx.x;
    if (i >= 1024 * 1024 / 4) return;
    const float* src = (t == 0) ? Wq : (t == 1) ? Wk : (t == 2) ? Wv : Wo;
    __half* dst = (t < 3) ? g_wh + (size_t)t * 1024 * 1024 : g_oh;
    float4 v = ((const float4*)src)[i];
    uint2 hv{pack_h(v.x, v.y), pack_h(v.z, v.w)};
    ((uint2*)dst)[i] = hv;
}

// ---------------- sliding-window attention, HMMA fp16 2-term ----------------
// smem: Q hi 8KB | Q lo 8KB | K hi 8KB | V hi 8KB = 32KB.
#define ASM_QH 0
#define ASM_QL 8192
#define ASM_K  16384
#define ASM_V  24576
#define SWZ(r, gd) ((r) * 128 + (((gd) ^ ((r) & 7)) * 16))

__global__ __launch_bounds__(128) void attn_kernel() {
    __shared__ __align__(16) char sm[32768];
    const uint32_t sb = smem_u32(sm);
    const int tid = threadIdx.x, lid = tid & 31, wid = tid >> 5;
    const int t0 = blockIdx.x * 64, h = blockIdx.y, b = blockIdx.z;

    {
        const size_t qr0 = (size_t)(b * SEQ + t0);
        #pragma unroll
        for (int it = 0; it < 4; it++) {
            int idx = it * 128 + tid;
            int r = idx >> 3, gd = idx & 7;
            uint32_t sw = SWZ(r, gd);
            size_t go = (qr0 + r) * 3072 + h * 64 + gd * 8;
            cp_async16(sb + ASM_QH + sw, g_h + go);
            cp_async16(sb + ASM_QL + sw, g_l + go);
        }
        asm volatile("cp.async.commit_group;\ncp.async.wait_group 0;" ::: "memory");
        __syncthreads();
    }
    uint32_t qh[4][4], ql[4][4];
    {
        int r = wid * 16 + (lid & 15);
        int gs = (lid >> 4) & 1;
        #pragma unroll
        for (int ks = 0; ks < 4; ks++) {
            uint32_t sw = SWZ(r, ks * 2 + gs);
            ldm4(qh[ks], sb + ASM_QH + sw);
            ldm4(ql[ks], sb + ASM_QL + sw);
        }
    }

    float mmax0 = -1e30f, mmax1 = -1e30f, lsum0 = 0.f, lsum1 = 0.f;
    float o[8][4];
    #pragma unroll
    for (int nt = 0; nt < 8; nt++)
        #pragma unroll
        for (int q = 0; q < 4; q++) o[nt][q] = 0.f;

    const int qrow_a = t0 + wid * 16 + (lid >> 2);
    const int qrow_b = qrow_a + 8;

    for (int cch = 0; cch < 3; cch++) {
        const int ks0 = t0 - 128 + cch * 64;
        if (ks0 < 0) continue;

        __syncthreads();
        {
            const size_t kr0 = (size_t)(b * SEQ + ks0);
            #pragma unroll
            for (int it = 0; it < 4; it++) {
                int idx = it * 128 + tid;
                int r = idx >> 3, gd = idx & 7;
                uint32_t sw = SWZ(r, gd);
                size_t go = (kr0 + r) * 3072 + h * 64 + gd * 8;
                cp_async16(sb + ASM_K + sw, g_h + go + 1024);
                cp_async16(sb + ASM_V + sw, g_h + go + 2048);
            }
            asm volatile("cp.async.commit_group;\ncp.async.wait_group 0;" ::: "memory");
            __syncthreads();
        }

        float s[8][4];
        #pragma unroll
        for (int nt = 0; nt < 8; nt++)
            #pragma unroll
            for (int q = 0; q < 4; q++) s[nt][q] = 0.f;

        #pragma unroll
        for (int ks = 0; ks < 4; ks++) {
            const int n  = (lid & 7) + 8 * ((lid >> 4) & 1);
            const int gd = ks * 2 + ((lid >> 3) & 1);
            #pragma unroll
            for (int np = 0; np < 4; np++) {
                uint32_t kh[4];
                int row = np * 16 + n;
                ldm4(kh, sb + ASM_K + SWZ(row, gd));
                uint32_t bh0[2] = {kh[0], kh[1]}, bh1[2] = {kh[2], kh[3]};
                mma16816(s[2 * np],     qh[ks], bh0);
                mma16816(s[2 * np],     ql[ks], bh0);
                mma16816(s[2 * np + 1], qh[ks], bh1);
                mma16816(s[2 * np + 1], ql[ks], bh1);
            }
        }

        float mloc0 = -1e30f, mloc1 = -1e30f;
        #pragma unroll
        for (int nt = 0; nt < 8; nt++)
            #pragma unroll
            for (int e = 0; e < 2; e++) {
                int kg = ks0 + nt * 8 + (lid & 3) * 2 + e;
                float v0 = s[nt][e] * 0.125f;
                float v1 = s[nt][2 + e] * 0.125f;
                if (kg > qrow_a || kg < qrow_a - 127) v0 = -1e30f;
                if (kg > qrow_b || kg < qrow_b - 127) v1 = -1e30f;
                s[nt][e] = v0; s[nt][2 + e] = v1;
                mloc0 = fmaxf(mloc0, v0);
                mloc1 = fmaxf(mloc1, v1);
            }
        mloc0 = fmaxf(mloc0, __shfl_xor_sync(0xffffffffu, mloc0, 1));
        mloc0 = fmaxf(mloc0, __shfl_xor_sync(0xffffffffu, mloc0, 2));
        mloc1 = fmaxf(mloc1, __shfl_xor_sync(0xffffffffu, mloc1, 1));
        mloc1 = fmaxf(mloc1, __shfl_xor_sync(0xffffffffu, mloc1, 2));
        float mn0 = fmaxf(mmax0, mloc0), mn1 = fmaxf(mmax1, mloc1);
        float al0 = __expf(mmax0 - mn0), al1 = __expf(mmax1 - mn1);
        float ps0 = 0.f, ps1 = 0.f;
        #pragma unroll
        for (int nt = 0; nt < 8; nt++)
            #pragma unroll
            for (int e = 0; e < 2; e++) {
                float p0 = __expf(s[nt][e] - mn0);
                float p1 = __expf(s[nt][2 + e] - mn1);
                s[nt][e] = p0; s[nt][2 + e] = p1;
                ps0 += p0; ps1 += p1;
            }
        ps0 += __shfl_xor_sync(0xffffffffu, ps0, 1);
        ps0 += __shfl_xor_sync(0xffffffffu, ps0, 2);
        ps1 += __shfl_xor_sync(0xffffffffu, ps1, 1);
        ps1 += __shfl_xor_sync(0xffffffffu, ps1, 2);
        mmax0 = mn0; mmax1 = mn1;
        lsum0 = lsum0 * al0 + ps0;
        lsum1 = lsum1 * al1 + ps1;
        #pragma unroll
        for (int nt = 0; nt < 8; nt++) {
            o[nt][0] *= al0; o[nt][1] *= al0;
            o[nt][2] *= al1; o[nt][3] *= al1;
        }

        uint32_t ph[4][4], pl[4][4];
        #pragma unroll
        for (int ks = 0; ks < 4; ks++) {
            pack_hl(s[2 * ks][0],     s[2 * ks][1],     ph[ks][0], pl[ks][0]);
            pack_hl(s[2 * ks][2],     s[2 * ks][3],     ph[ks][1], pl[ks][1]);
            pack_hl(s[2 * ks + 1][0], s[2 * ks + 1][1], ph[ks][2], pl[ks][2]);
            pack_hl(s[2 * ks + 1][2], s[2 * ks + 1][3], ph[ks][3], pl[ks][3]);
        }

        #pragma unroll
        for (int ks = 0; ks < 4; ks++) {
            const int tile = lid >> 3;
            const int r = ks * 16 + (tile & 1) * 8 + (lid & 7);
            #pragma unroll
            for (int dp = 0; dp < 4; dp++) {
                uint32_t vh[4];
                ldm4t(vh, sb + ASM_V + SWZ(r, dp * 2 + (tile >> 1)));
                uint32_t bh0[2] = {vh[0], vh[1]}, bh1[2] = {vh[2], vh[3]};
                mma16816(o[2 * dp],     ph[ks], bh0);
                mma16816(o[2 * dp],     pl[ks], bh0);
                mma16816(o[2 * dp + 1], ph[ks], bh1);
                mma16816(o[2 * dp + 1], pl[ks], bh1);
            }
        }
    }

    const float il0 = 1.0f / lsum0, il1 = 1.0f / lsum1;
    const size_t r0 = (size_t)(b * SEQ + t0 + wid * 16 + (lid >> 2));
    const size_t r1 = r0 + 8;
    const int c0 = h * 64 + (lid & 3) * 2;
    #pragma unroll
    for (int nt = 0; nt < 8; nt++) {
        int c = c0 + nt * 8;
        uint32_t hv, lv;
        pack_hl(o[nt][0] * il0, o[nt][1] * il0, hv, lv);
        *(uint32_t*)(g_ah + r0 * 1024 + c) = hv;
        *(uint32_t*)(g_al + r0 * 1024 + c) = lv;
        pack_hl(o[nt][2] * il1, o[nt][3] * il1, hv, lv);
        *(uint32_t*)(g_ah + r1 * 1024 + c) = hv;
        *(uint32_t*)(g_al + r1 * 1024 + c) = lv;
    }
}

// ---------------------------------------------------------------------------
extern "C" void kernel_launch(void* const* d_in, const int* in_sizes, int n_in,
                              void* d_out, int out_size) {
    (void)in_sizes; (void)n_in; (void)out_size;
    const float* X  = (const float*)d_in[0];
    const float* Wq = (const float*)d_in[1];
    const float* Wk = (const float*)d_in[2];
    const float* Wv = (const float*)d_in[3];
    const float* Wo = (const float*)d_in[4];
    const float* bo = (const float*)d_in[5];
    float* out = (float*)d_out;

    cudaFuncSetAttribute(qkv_hmma,   cudaFuncAttributeMaxDynamicSharedMemorySize, GSMEM_B);
    cudaFuncSetAttribute(oproj_hmma, cudaFuncAttributeMaxDynamicSharedMemorySize, GSMEM_B);

    split_x<<<4096, 256>>>(X);
    conv_w<<<4096, 256>>>(Wq, Wk, Wv, Wo);

    qkv_hmma<<<GRIDX, 256, GSMEM_B>>>();
    attn_kernel<<<dim3(SEQ / 64, NH, NB), 128>>>();
    oproj_hmma<<<GRIDX, 256, GSMEM_B>>>(out, bo);
}